// round 1
// baseline (speedup 1.0000x reference)
#include <cuda_runtime.h>
#include <math.h>

#define Bb   4
#define Tt   8192
#define Dd   512
#define Hh   8
#define DH   64
#define TEE  2048
#define NTOK (Bb*Tt)

// ---------------- scratch (global device arrays; no allocations) ----------------
__device__ float g_xn[NTOK*Dd];            // LN(x)
__device__ float g_qs[NTOK*Dd];            // softmaxed q
__device__ float g_ek[NTOK*Dd];            // exp(k) (masked -> 0)
__device__ float g_vv[NTOK*Dd];            // masked v
__device__ float g_y [NTOK*Dd];            // attention output
__device__ float g_hs[NTOK*Dd];            // silu(stylized LN(y))
__device__ float g_ksum[Bb*Dd];            // column sums of exp(k)
__device__ float g_attn[Bb*Hh*DH*DH];      // unnormalized KV state
__device__ float g_emb[Bb*2*Dd];           // emb_out (scale|shift)

// ---------------- zero accumulators (replayed every graph launch) ----------------
__global__ void zero_k() {
    int i = blockIdx.x * blockDim.x + threadIdx.x;
    if (i < Bb*Dd) g_ksum[i] = 0.f;
    if (i < Bb*Hh*DH*DH) g_attn[i] = 0.f;
}

// ---------------- emb_out = silu(emb) @ emb_W + emb_b ----------------
__global__ void emb_k(const float* __restrict__ emb,
                      const float* __restrict__ W,
                      const float* __restrict__ bias) {
    __shared__ float se[TEE];
    int b = blockIdx.x, tid = threadIdx.x;
    for (int i = tid; i < TEE; i += 256) {
        float e = emb[b*TEE + i];
        se[i] = e / (1.f + expf(-e));
    }
    __syncthreads();
    int o = blockIdx.y * 256 + tid;
    float acc = bias[o];
    #pragma unroll 4
    for (int e = 0; e < TEE; e++)
        acc += se[e] * W[(size_t)e*(2*Dd) + o];
    g_emb[b*2*Dd + o] = acc;
}

// ---------------- LN(x) -> g_xn  (one block of 128 threads per token) ----------------
__global__ void ln_k(const float* __restrict__ x,
                     const float* __restrict__ g,
                     const float* __restrict__ be) {
    int tok = blockIdx.x, tid = threadIdx.x;
    float4 v = ((const float4*)(x + (size_t)tok*Dd))[tid];
    float s = v.x + v.y + v.z + v.w;
    __shared__ float r1[4], r2[4];
    for (int o = 16; o; o >>= 1) s += __shfl_xor_sync(0xffffffffu, s, o);
    if ((tid & 31) == 0) r1[tid >> 5] = s;
    __syncthreads();
    float mu = (r1[0] + r1[1] + r1[2] + r1[3]) * (1.f / Dd);
    float a = v.x - mu, b = v.y - mu, c = v.z - mu, d = v.w - mu;
    float ss = a*a + b*b + c*c + d*d;
    for (int o = 16; o; o >>= 1) ss += __shfl_xor_sync(0xffffffffu, ss, o);
    if ((tid & 31) == 0) r2[tid >> 5] = ss;
    __syncthreads();
    float var = (r2[0] + r2[1] + r2[2] + r2[3]) * (1.f / Dd);
    float rs = rsqrtf(var + 1e-5f);
    float4 gg = ((const float4*)g)[tid], bb = ((const float4*)be)[tid];
    float4 o4;
    o4.x = a*rs*gg.x + bb.x; o4.y = b*rs*gg.y + bb.y;
    o4.z = c*rs*gg.z + bb.z; o4.w = d*rs*gg.w + bb.w;
    ((float4*)(g_xn + (size_t)tok*Dd))[tid] = o4;
}

// ---------------- fused QKV GEMM: [32768,512] @ [512,1536] with per-region epilogues ---
// BM=128, BN=64, BK=16, 128 threads, 8x8 thread tile.
__global__ __launch_bounds__(128) void qkv_k(
    const float* __restrict__ Wq, const float* __restrict__ bq,
    const float* __restrict__ Wk, const float* __restrict__ bk,
    const float* __restrict__ Wv, const float* __restrict__ bv,
    const float* __restrict__ mask)
{
    const int BM = 128, BN = 64, BK = 16;
    __shared__ float As[BK][BM];
    __shared__ float Bs[BK][BN];
    __shared__ float Cs[BM][BN + 1];
    __shared__ float rowinv[BM];

    int n0 = blockIdx.x * BN;
    int m0 = blockIdx.y * BM;
    int region = n0 >> 9;           // 0=q, 1=k, 2=v
    int nn0 = n0 & 511;
    const float* W    = region == 0 ? Wq : (region == 1 ? Wk : Wv);
    const float* bias = region == 0 ? bq : (region == 1 ? bk : bv);

    int tid = threadIdx.x;
    int ty = tid >> 3, tx = tid & 7;
    float acc[8][8] = {};

    for (int k0 = 0; k0 < Dd; k0 += BK) {
        #pragma unroll
        for (int i = 0; i < 4; i++) {               // A: 128x16 transposed
            int f = tid + i * 128;
            int r = f >> 2, c4 = f & 3;
            float4 a = *(const float4*)(g_xn + (size_t)(m0 + r)*Dd + k0 + c4*4);
            As[c4*4+0][r] = a.x; As[c4*4+1][r] = a.y;
            As[c4*4+2][r] = a.z; As[c4*4+3][r] = a.w;
        }
        #pragma unroll
        for (int i = 0; i < 2; i++) {               // B: 16x64
            int f = tid + i * 128;
            int r = f >> 4, c4 = f & 15;
            *(float4*)&Bs[r][c4*4] = *(const float4*)(W + (size_t)(k0 + r)*Dd + nn0 + c4*4);
        }
        __syncthreads();
        #pragma unroll
        for (int kk = 0; kk < BK; kk++) {
            float a[8], b[8];
            #pragma unroll
            for (int i = 0; i < 8; i++) a[i] = As[kk][ty*8 + i];
            #pragma unroll
            for (int j = 0; j < 8; j++) b[j] = Bs[kk][tx*8 + j];
            #pragma unroll
            for (int i = 0; i < 8; i++)
                #pragma unroll
                for (int j = 0; j < 8; j++) acc[i][j] += a[i] * b[j];
        }
        __syncthreads();
    }

    // stage tile to shared for row-wise epilogues
    #pragma unroll
    for (int i = 0; i < 8; i++)
        #pragma unroll
        for (int j = 0; j < 8; j++) Cs[ty*8 + i][tx*8 + j] = acc[i][j];
    __syncthreads();

    if (region == 0) {
        // q: + bq, softmax over the head's 64 cols (tile == one head)
        {
            int r = tid;
            float mx = -1e30f;
            #pragma unroll 8
            for (int j = 0; j < 64; j++) mx = fmaxf(mx, Cs[r][j] + bias[nn0 + j]);
            float sum = 0.f;
            #pragma unroll 8
            for (int j = 0; j < 64; j++) {
                float e = expf(Cs[r][j] + bias[nn0 + j] - mx);
                Cs[r][j] = e; sum += e;
            }
            rowinv[r] = 1.f / sum;
        }
        __syncthreads();
        for (int e = tid; e < BM*64; e += 128) {
            int r = e >> 6, j = e & 63;
            g_qs[(size_t)(m0 + r)*Dd + nn0 + j] = Cs[r][j] * rowinv[r];
        }
    } else if (region == 1) {
        // k: + bk + (1-mask)(-1e6), exp (masked -> exactly 0), column-sum into g_ksum
        {
            int r = tid;
            float mv = mask[m0 + r];
            float madd = (1.f - mv) * (-1e6f);
            #pragma unroll 8
            for (int j = 0; j < 64; j++)
                Cs[r][j] = expf(Cs[r][j] + bias[nn0 + j] + madd);
        }
        __syncthreads();
        if (tid < 64) {
            float s = 0.f;
            #pragma unroll 8
            for (int r = 0; r < BM; r++) s += Cs[r][tid];
            atomicAdd(&g_ksum[(m0 >> 13)*Dd + nn0 + tid], s);
        }
        for (int e = tid; e < BM*64; e += 128) {
            int r = e >> 6, j = e & 63;
            g_ek[(size_t)(m0 + r)*Dd + nn0 + j] = Cs[r][j];
        }
    } else {
        // v: (+ bv) * mask
        for (int e = tid; e < BM*64; e += 128) {
            int r = e >> 6, j = e & 63;
            float mv = mask[m0 + r];
            g_vv[(size_t)(m0 + r)*Dd + nn0 + j] = (Cs[r][j] + bias[nn0 + j]) * mv;
        }
    }
}

// ---------------- KV state: attn[b,h] += ek_h^T @ v_h over a T-chunk ----------------
__global__ __launch_bounds__(256) void kv_k() {
    int bh = blockIdx.x; int b = bh >> 3; int h = bh & 7;
    const int TC = Tt / 16;
    int t0 = b*Tt + blockIdx.y * TC;
    __shared__ float Es[16][64];
    __shared__ float Vs[16][64];
    int tid = threadIdx.x, ty = tid >> 4, tx = tid & 15;
    float acc[4][4] = {};
    for (int kt = 0; kt < TC; kt += 16) {
        int r = tid >> 4, c4 = tid & 15;
        size_t base = (size_t)(t0 + kt + r)*Dd + h*DH + c4*4;
        *(float4*)&Es[r][c4*4] = *(const float4*)(g_ek + base);
        *(float4*)&Vs[r][c4*4] = *(const float4*)(g_vv + base);
        __syncthreads();
        #pragma unroll
        for (int kk = 0; kk < 16; kk++) {
            float a[4], v4[4];
            #pragma unroll
            for (int i = 0; i < 4; i++) a[i]  = Es[kk][ty*4 + i];
            #pragma unroll
            for (int j = 0; j < 4; j++) v4[j] = Vs[kk][tx*4 + j];
            #pragma unroll
            for (int i = 0; i < 4; i++)
                #pragma unroll
                for (int j = 0; j < 4; j++) acc[i][j] += a[i] * v4[j];
        }
        __syncthreads();
    }
    float* A = g_attn + (size_t)bh*DH*DH;
    #pragma unroll
    for (int i = 0; i < 4; i++)
        #pragma unroll
        for (int j = 0; j < 4; j++)
            atomicAdd(&A[(ty*4 + i)*DH + tx*4 + j], acc[i][j]);
}

// ---------------- y = q_h @ (attn_h / ksum) per head; 128 tokens per block ----------
__global__ __launch_bounds__(256) void y_k() {
    int bh = blockIdx.x; int b = bh >> 3; int h = bh & 7;
    int t0 = b*Tt + blockIdx.y * 128;
    __shared__ float Ah[DH][DH];
    __shared__ float Qs[16][128];
    int tid = threadIdx.x, ty = tid >> 4, tx = tid & 15;

    {   // load KV state, fold in 1/ksum row-normalization
        const float* A  = g_attn + (size_t)bh*DH*DH;
        const float* ks = g_ksum + b*Dd + h*DH;
        #pragma unroll
        for (int i = 0; i < 4; i++) {
            int f = tid + i * 256;          // float4 index over 64x64
            int d = f >> 4, l4 = f & 15;
            float rk = 1.f / ks[d];
            float4 a = *(const float4*)(A + d*DH + l4*4);
            a.x *= rk; a.y *= rk; a.z *= rk; a.w *= rk;
            *(float4*)&Ah[d][l4*4] = a;
        }
    }
    float acc[8][4] = {};
    for (int k0 = 0; k0 < DH; k0 += 16) {
        #pragma unroll
        for (int i = 0; i < 2; i++) {       // q tile 128x16 transposed
            int f = tid + i * 256;
            int r = f >> 2, c4 = f & 3;
            float4 q = *(const float4*)(g_qs + (size_t)(t0 + r)*Dd + h*DH + k0 + c4*4);
            Qs[c4*4+0][r] = q.x; Qs[c4*4+1][r] = q.y;
            Qs[c4*4+2][r] = q.z; Qs[c4*4+3][r] = q.w;
        }
        __syncthreads();
        #pragma unroll
        for (int kk = 0; kk < 16; kk++) {
            float a[8], bb[4];
            #pragma unroll
            for (int i = 0; i < 8; i++) a[i]  = Qs[kk][ty*8 + i];
            #pragma unroll
            for (int j = 0; j < 4; j++) bb[j] = Ah[k0 + kk][tx*4 + j];
            #pragma unroll
            for (int i = 0; i < 8; i++)
                #pragma unroll
                for (int j = 0; j < 4; j++) acc[i][j] += a[i] * bb[j];
        }
        __syncthreads();
    }
    #pragma unroll
    for (int i = 0; i < 8; i++) {
        int tokr = t0 + ty*8 + i;
        float4 o; o.x = acc[i][0]; o.y = acc[i][1]; o.z = acc[i][2]; o.w = acc[i][3];
        *(float4*)(g_y + (size_t)tokr*Dd + h*DH + tx*4) = o;
    }
}

// ---------------- stylize: LN(y)*(1+scale)+shift, then silu -> g_hs ----------------
__global__ void style_k(const float* __restrict__ g2, const float* __restrict__ b2) {
    int tok = blockIdx.x, tid = threadIdx.x;
    int b = tok >> 13;
    float4 v = ((const float4*)(g_y + (size_t)tok*Dd))[tid];
    float s = v.x + v.y + v.z + v.w;
    __shared__ float r1[4], r2[4];
    for (int o = 16; o; o >>= 1) s += __shfl_xor_sync(0xffffffffu, s, o);
    if ((tid & 31) == 0) r1[tid >> 5] = s;
    __syncthreads();
    float mu = (r1[0] + r1[1] + r1[2] + r1[3]) * (1.f / Dd);
    float a = v.x - mu, bb_ = v.y - mu, c = v.z - mu, d = v.w - mu;
    float ss = a*a + bb_*bb_ + c*c + d*d;
    for (int o = 16; o; o >>= 1) ss += __shfl_xor_sync(0xffffffffu, ss, o);
    if ((tid & 31) == 0) r2[tid >> 5] = ss;
    __syncthreads();
    float var = (r2[0] + r2[1] + r2[2] + r2[3]) * (1.f / Dd);
    float rs = rsqrtf(var + 1e-5f);
    float4 gg = ((const float4*)g2)[tid], bt = ((const float4*)b2)[tid];
    float4 sc = ((const float4*)(g_emb + b*2*Dd))[tid];
    float4 sh = ((const float4*)(g_emb + b*2*Dd + Dd))[tid];
    float h0 = (a  *rs*gg.x + bt.x)*(1.f + sc.x) + sh.x;
    float h1 = (bb_*rs*gg.y + bt.y)*(1.f + sc.y) + sh.y;
    float h2 = (c  *rs*gg.z + bt.z)*(1.f + sc.z) + sh.z;
    float h3 = (d  *rs*gg.w + bt.w)*(1.f + sc.w) + sh.w;
    h0 = h0 / (1.f + expf(-h0));
    h1 = h1 / (1.f + expf(-h1));
    h2 = h2 / (1.f + expf(-h2));
    h3 = h3 / (1.f + expf(-h3));
    float4 o4; o4.x = h0; o4.y = h1; o4.z = h2; o4.w = h3;
    ((float4*)(g_hs + (size_t)tok*Dd))[tid] = o4;
}

// ---------------- out = x + g_hs @ out_W + out_b ----------------
__global__ __launch_bounds__(128) void out_k(
    const float* __restrict__ W, const float* __restrict__ bias,
    const float* __restrict__ x, float* __restrict__ out)
{
    const int BM = 128, BN = 64, BK = 16;
    __shared__ float As[BK][BM];
    __shared__ float Bs[BK][BN];
    int n0 = blockIdx.x * BN;
    int m0 = blockIdx.y * BM;
    int tid = threadIdx.x;
    int ty = tid >> 3, tx = tid & 7;
    float acc[8][8] = {};

    for (int k0 = 0; k0 < Dd; k0 += BK) {
        #pragma unroll
        for (int i = 0; i < 4; i++) {
            int f = tid + i * 128;
            int r = f >> 2, c4 = f & 3;
            float4 a = *(const float4*)(g_hs + (size_t)(m0 + r)*Dd + k0 + c4*4);
            As[c4*4+0][r] = a.x; As[c4*4+1][r] = a.y;
            As[c4*4+2][r] = a.z; As[c4*4+3][r] = a.w;
        }
        #pragma unroll
        for (int i = 0; i < 2; i++) {
            int f = tid + i * 128;
            int r = f >> 4, c4 = f & 15;
            *(float4*)&Bs[r][c4*4] = *(const float4*)(W + (size_t)(k0 + r)*Dd + n0 + c4*4);
        }
        __syncthreads();
        #pragma unroll
        for (int kk = 0; kk < BK; kk++) {
            float a[8], b[8];
            #pragma unroll
            for (int i = 0; i < 8; i++) a[i] = As[kk][ty*8 + i];
            #pragma unroll
            for (int j = 0; j < 8; j++) b[j] = Bs[kk][tx*8 + j];
            #pragma unroll
            for (int i = 0; i < 8; i++)
                #pragma unroll
                for (int j = 0; j < 8; j++) acc[i][j] += a[i] * b[j];
        }
        __syncthreads();
    }
    #pragma unroll
    for (int i = 0; i < 8; i++) {
        size_t off = (size_t)(m0 + ty*8 + i)*Dd + n0 + tx*8;
        float4 x0 = *(const float4*)(x + off), x1 = *(const float4*)(x + off + 4);
        float4 b0 = *(const float4*)(bias + n0 + tx*8), b1 = *(const float4*)(bias + n0 + tx*8 + 4);
        float4 o0, o1;
        o0.x = x0.x + b0.x + acc[i][0]; o0.y = x0.y + b0.y + acc[i][1];
        o0.z = x0.z + b0.z + acc[i][2]; o0.w = x0.w + b0.w + acc[i][3];
        o1.x = x1.x + b1.x + acc[i][4]; o1.y = x1.y + b1.y + acc[i][5];
        o1.z = x1.z + b1.z + acc[i][6]; o1.w = x1.w + b1.w + acc[i][7];
        *(float4*)(out + off)     = o0;
        *(float4*)(out + off + 4) = o1;
    }
}

// ---------------- launch ----------------
extern "C" void kernel_launch(void* const* d_in, const int* in_sizes, int n_in,
                              void* d_out, int out_size) {
    const float* x     = (const float*)d_in[0];
    const float* emb   = (const float*)d_in[1];
    const float* mask  = (const float*)d_in[2];
    const float* gamma = (const float*)d_in[3];
    const float* beta  = (const float*)d_in[4];
    const float* Wq    = (const float*)d_in[5];
    const float* bq    = (const float*)d_in[6];
    const float* Wk    = (const float*)d_in[7];
    const float* bk    = (const float*)d_in[8];
    const float* Wv    = (const float*)d_in[9];
    const float* bv    = (const float*)d_in[10];
    const float* embW  = (const float*)d_in[11];
    const float* embB  = (const float*)d_in[12];
    const float* g2    = (const float*)d_in[13];
    const float* b2    = (const float*)d_in[14];
    const float* outW  = (const float*)d_in[15];
    const float* outB  = (const float*)d_in[16];
    float* out = (float*)d_out;

    zero_k <<<512, 256>>>();
    emb_k  <<<dim3(Bb, 4), 256>>>(emb, embW, embB);
    ln_k   <<<NTOK, 128>>>(x, gamma, beta);
    qkv_k  <<<dim3(24, NTOK/128), 128>>>(Wq, bq, Wk, bk, Wv, bv, mask);
    kv_k   <<<dim3(Bb*Hh, 16), 256>>>();
    y_k    <<<dim3(Bb*Hh, Tt/128), 256>>>();
    style_k<<<NTOK, 128>>>(g2, b2);
    out_k  <<<dim3(Dd/64, NTOK/128), 128>>>(outW, outB, x, out);
}

// round 3
// speedup vs baseline: 3.1991x; 3.1991x over previous
#include <cuda_runtime.h>
#include <cuda_bf16.h>
#include <math.h>
#include <stdint.h>

#define Bb   4
#define Tt   8192
#define Dd   512
#define Hh   8
#define DH   64
#define TEE  2048
#define NTOK (Bb*Tt)

// ---------------- scratch (tf32-rounded fp32 operands + fp32 intermediates) ----
__device__ float g_xn[NTOK*Dd];            // LN(x), tf32-rounded
__device__ float g_hs[NTOK*Dd];            // silu(stylized), tf32-rounded
__device__ float g_qkvT[3*Dd*Dd];          // [1536][512] W^T, tf32-rounded
__device__ float g_outT[Dd*Dd];            // [512][512]  W^T, tf32-rounded
__device__ float g_qs[NTOK*Dd];
__device__ float g_ek[NTOK*Dd];
__device__ float g_vv[NTOK*Dd];
__device__ float g_y [NTOK*Dd];
__device__ float g_ksum[Bb*Dd];
__device__ float g_attn[Bb*Hh*DH*DH];
__device__ float g_emb[Bb*2*Dd];

// ---------------- helpers ----------------
__device__ __forceinline__ float tf32_round(float f) {
    uint32_t u;
    asm("cvt.rna.tf32.f32 %0, %1;" : "=r"(u) : "f"(f));
    return __uint_as_float(u);
}
__device__ __forceinline__ void cp16(void* dst, const void* src) {
    uint32_t d;
    asm("{ .reg .u64 t; cvta.to.shared.u64 t, %1; cvt.u32.u64 %0, t; }" : "=r"(d) : "l"(dst));
    asm volatile("cp.async.cg.shared.global [%0], [%1], 16;" :: "r"(d), "l"(src) : "memory");
}
__device__ __forceinline__ void mma_tf32(float* c, const uint32_t* a, const uint32_t* b) {
    asm volatile(
        "mma.sync.aligned.m16n8k8.row.col.f32.tf32.tf32.f32 "
        "{%0,%1,%2,%3}, {%4,%5,%6,%7}, {%8,%9}, {%0,%1,%2,%3};"
        : "+f"(c[0]), "+f"(c[1]), "+f"(c[2]), "+f"(c[3])
        : "r"(a[0]), "r"(a[1]), "r"(a[2]), "r"(a[3]), "r"(b[0]), "r"(b[1]));
}

// ---------------- zero accumulators ----------------
__global__ void zero_k() {
    int i = blockIdx.x * blockDim.x + threadIdx.x;
    if (i < Bb*Dd) g_ksum[i] = 0.f;
    if (i < Bb*Hh*DH*DH) g_attn[i] = 0.f;
}

// ---------------- weight transpose + tf32 round ----------------
__global__ void wconv_k(const float* __restrict__ Wq, const float* __restrict__ Wk,
                        const float* __restrict__ Wv, const float* __restrict__ Wo) {
    __shared__ float t[32][33];
    int mat = blockIdx.z;
    const float* W = mat == 0 ? Wq : mat == 1 ? Wk : mat == 2 ? Wv : Wo;
    int k0 = blockIdx.y * 32, n0 = blockIdx.x * 32;
    int tx = threadIdx.x, ty = threadIdx.y;
    #pragma unroll
    for (int i = 0; i < 4; i++)
        t[ty + i*8][tx] = W[(size_t)(k0 + ty + i*8)*Dd + n0 + tx];
    __syncthreads();
    float* dst = (mat < 3) ? g_qkvT : g_outT;
    int nbase = (mat < 3) ? mat*Dd : 0;
    #pragma unroll
    for (int i = 0; i < 4; i++) {
        int n = n0 + ty + i*8, k = k0 + tx;
        dst[(size_t)(nbase + n)*Dd + k] = tf32_round(t[tx][ty + i*8]);
    }
}

// ---------------- emb_out = silu(emb) @ emb_W + emb_b ----------------
__global__ void emb_k(const float* __restrict__ emb,
                      const float* __restrict__ W,
                      const float* __restrict__ bias) {
    __shared__ float se[TEE];
    int b = blockIdx.x, tid = threadIdx.x;
    for (int i = tid; i < TEE; i += 256) {
        float e = emb[b*TEE + i];
        se[i] = e / (1.f + expf(-e));
    }
    __syncthreads();
    int o = blockIdx.y * 256 + tid;
    float acc = bias[o];
    #pragma unroll 4
    for (int e = 0; e < TEE; e++)
        acc += se[e] * W[(size_t)e*(2*Dd) + o];
    g_emb[b*2*Dd + o] = acc;
}

// ---------------- LN(x) -> g_xn (tf32-rounded) ----------------
__global__ void ln_k(const float* __restrict__ x,
                     const float* __restrict__ g,
                     const float* __restrict__ be) {
    int tok = blockIdx.x, tid = threadIdx.x;
    float4 v = ((const float4*)(x + (size_t)tok*Dd))[tid];
    float s = v.x + v.y + v.z + v.w;
    __shared__ float r1[4], r2[4];
    for (int o = 16; o; o >>= 1) s += __shfl_xor_sync(0xffffffffu, s, o);
    if ((tid & 31) == 0) r1[tid >> 5] = s;
    __syncthreads();
    float mu = (r1[0] + r1[1] + r1[2] + r1[3]) * (1.f / Dd);
    float a = v.x - mu, b = v.y - mu, c = v.z - mu, d = v.w - mu;
    float ss = a*a + b*b + c*c + d*d;
    for (int o = 16; o; o >>= 1) ss += __shfl_xor_sync(0xffffffffu, ss, o);
    if ((tid & 31) == 0) r2[tid >> 5] = ss;
    __syncthreads();
    float var = (r2[0] + r2[1] + r2[2] + r2[3]) * (1.f / Dd);
    float rs = rsqrtf(var + 1e-5f);
    float4 gg = ((const float4*)g)[tid], bb = ((const float4*)be)[tid];
    float4 o4;
    o4.x = tf32_round(a*rs*gg.x + bb.x); o4.y = tf32_round(b*rs*gg.y + bb.y);
    o4.z = tf32_round(c*rs*gg.z + bb.z); o4.w = tf32_round(d*rs*gg.w + bb.w);
    ((float4*)(g_xn + (size_t)tok*Dd))[tid] = o4;
}

// ---------------- HMMA tf32 GEMM: BM=128, BN=128, BK=32, 3-stage cp.async ------
// smem: 3 stages of (A[128][36] + B[128][36]) floats, then reused as Cs[128][132]
#define STG_F (128*36)             // floats per operand per stage
#define STAGE_F (2*STG_F)          // A+B
#define SMEM_BYTES (3*STAGE_F*4 > 128*132*4 ? 3*STAGE_F*4 : 128*132*4)

__device__ __forceinline__ void copy_stage(float* sm, int st, int kc,
    const float* __restrict__ Ag, const float* __restrict__ Bg,
    int m0, int n0, int tid)
{
    float* A = sm + st*STAGE_F;
    float* B = A + STG_F;
    #pragma unroll
    for (int i = 0; i < 4; i++) {
        int s = tid + i*256;
        int r = s >> 3, c8 = s & 7;
        cp16(A + r*36 + c8*4, Ag + (size_t)(m0 + r)*Dd + kc*32 + c8*4);
        cp16(B + r*36 + c8*4, Bg + (size_t)(n0 + r)*Dd + kc*32 + c8*4);
    }
    asm volatile("cp.async.commit_group;" ::: "memory");
}

__global__ __launch_bounds__(256) void gemm_k(
    int mode,                       // 0 = QKV, 1 = OUT
    const float* __restrict__ b0, const float* __restrict__ b1, const float* __restrict__ b2,
    const float* __restrict__ mask, const float* __restrict__ xres, float* __restrict__ outp)
{
    extern __shared__ float sm[];
    int tid = threadIdx.x;
    int lane = tid & 31, w = tid >> 5;
    int g = lane >> 2, cq = lane & 3;
    int wm = w & 1, wn = w >> 1;          // 2 x 4 warps
    int mBase = wm*64, nBase = wn*32;
    int m0 = blockIdx.y * 128;
    int n0 = blockIdx.x * 128;

    const float* Ag = mode ? g_hs : g_xn;
    const float* Bg = mode ? g_outT : g_qkvT;

    float acc[4][4][4];
    #pragma unroll
    for (int i = 0; i < 4; i++)
        #pragma unroll
        for (int j = 0; j < 4; j++)
            #pragma unroll
            for (int r = 0; r < 4; r++) acc[i][j][r] = 0.f;

    copy_stage(sm, 0, 0, Ag, Bg, m0, n0, tid);
    copy_stage(sm, 1, 1, Ag, Bg, m0, n0, tid);

    const int NIT = Dd/32;                 // 16
    for (int it = 0; it < NIT; it++) {
        if (it + 2 < NIT) copy_stage(sm, (it+2)%3, it+2, Ag, Bg, m0, n0, tid);
        if (it + 2 < NIT)      asm volatile("cp.async.wait_group 2;" ::: "memory");
        else if (it + 1 < NIT) asm volatile("cp.async.wait_group 1;" ::: "memory");
        else                   asm volatile("cp.async.wait_group 0;" ::: "memory");
        __syncthreads();

        const uint32_t* As = (const uint32_t*)(sm + (it%3)*STAGE_F);
        const uint32_t* Bs = As + STG_F;
        #pragma unroll
        for (int k8 = 0; k8 < 4; k8++) {
            int kk = k8*8;
            uint32_t a[4][4], b[4][2];
            #pragma unroll
            for (int mt = 0; mt < 4; mt++) {
                int r = mBase + mt*16 + g;
                a[mt][0] = As[r*36 + kk + cq];
                a[mt][1] = As[(r+8)*36 + kk + cq];
                a[mt][2] = As[r*36 + kk + cq + 4];
                a[mt][3] = As[(r+8)*36 + kk + cq + 4];
            }
            #pragma unroll
            for (int nt = 0; nt < 4; nt++) {
                int r = nBase + nt*8 + g;
                b[nt][0] = Bs[r*36 + kk + cq];
                b[nt][1] = Bs[r*36 + kk + cq + 4];
            }
            #pragma unroll
            for (int mt = 0; mt < 4; mt++)
                #pragma unroll
                for (int nt = 0; nt < 4; nt++)
                    mma_tf32(acc[mt][nt], a[mt], b[nt]);
        }
        __syncthreads();
    }

    // stage C tile to shared (reuse pipeline smem)
    float (*Cs)[132] = (float (*)[132])sm;
    #pragma unroll
    for (int mt = 0; mt < 4; mt++) {
        int r = mBase + mt*16 + g;
        #pragma unroll
        for (int nt = 0; nt < 4; nt++) {
            int cc = nBase + nt*8 + cq*2;
            Cs[r][cc]     = acc[mt][nt][0];
            Cs[r][cc+1]   = acc[mt][nt][1];
            Cs[r+8][cc]   = acc[mt][nt][2];
            Cs[r+8][cc+1] = acc[mt][nt][3];
        }
    }
    __syncthreads();

    // epilogue: thread t handles row = t>>1, 64-col half = t&1
    int row = tid >> 1, half = tid & 1;
    int m = m0 + row;
    int ngl = n0 + half*64;
    const float* crow = &Cs[row][half*64];

    if (mode == 1) {
        float v[64];
        #pragma unroll
        for (int j = 0; j < 64; j++) v[j] = crow[j];
        #pragma unroll
        for (int j = 0; j < 64; j += 4) {
            size_t off = (size_t)m*Dd + ngl + j;
            float4 xr = *(const float4*)(xres + off);
            float4 o;
            o.x = v[j]   + b0[ngl+j]   + xr.x;
            o.y = v[j+1] + b0[ngl+j+1] + xr.y;
            o.z = v[j+2] + b0[ngl+j+2] + xr.z;
            o.w = v[j+3] + b0[ngl+j+3] + xr.w;
            *(float4*)(outp + off) = o;
        }
    } else {
        int region = n0 >> 9;
        int c5 = ngl & 511;
        if (region == 0) {
            float v[64];
            float mx = -1e30f;
            #pragma unroll
            for (int j = 0; j < 64; j++) { v[j] = crow[j] + b0[c5+j]; mx = fmaxf(mx, v[j]); }
            float s = 0.f;
            #pragma unroll
            for (int j = 0; j < 64; j++) { v[j] = expf(v[j] - mx); s += v[j]; }
            float inv = 1.f / s;
            #pragma unroll
            for (int j = 0; j < 64; j += 4) {
                float4 o; o.x = v[j]*inv; o.y = v[j+1]*inv; o.z = v[j+2]*inv; o.w = v[j+3]*inv;
                *(float4*)(g_qs + (size_t)m*Dd + c5 + j) = o;
            }
        } else if (region == 1) {
            float madd = (1.f - mask[m]) * (-1e6f);
            float v[64];
            #pragma unroll
            for (int j = 0; j < 64; j++) v[j] = expf(crow[j] + b1[c5+j] + madd);
            #pragma unroll
            for (int j = 0; j < 64; j += 4) {
                float4 o; o.x = v[j]; o.y = v[j+1]; o.z = v[j+2]; o.w = v[j+3];
                *(float4*)(g_ek + (size_t)m*Dd + c5 + j) = o;
            }
            // write exp values back for column sums
            float* cw = &Cs[row][half*64];
            #pragma unroll
            for (int j = 0; j < 64; j++) cw[j] = v[j];
        } else {
            float mv = mask[m];
            #pragma unroll
            for (int j = 0; j < 64; j += 4) {
                float4 o;
                o.x = (crow[j]   + b2[c5+j]  ) * mv;
                o.y = (crow[j+1] + b2[c5+j+1]) * mv;
                o.z = (crow[j+2] + b2[c5+j+2]) * mv;
                o.w = (crow[j+3] + b2[c5+j+3]) * mv;
                *(float4*)(g_vv + (size_t)m*Dd + c5 + j) = o;
            }
        }
        if (region == 1) {
            __syncthreads();
            if (tid < 128) {
                float s = 0.f;
                #pragma unroll 8
                for (int r = 0; r < 128; r++) s += Cs[r][tid];
                atomicAdd(&g_ksum[(m0 >> 13)*Dd + (n0 & 511) + tid], s);
            }
        }
    }
}

// ---------------- KV state: attn[b,h] += ek_h^T @ v_h ----------------
__global__ __launch_bounds__(256) void kv_k() {
    int bh = blockIdx.x; int b = bh >> 3; int h = bh & 7;
    const int TC = Tt / 16;
    int t0 = b*Tt + blockIdx.y * TC;
    __shared__ float Es[16][64];
    __shared__ float Vs[16][64];
    int tid = threadIdx.x, ty = tid >> 4, tx = tid & 15;
    float acc[4][4] = {};
    for (int kt = 0; kt < TC; kt += 16) {
        int r = tid >> 4, c4 = tid & 15;
        size_t base = (size_t)(t0 + kt + r)*Dd + h*DH + c4*4;
        *(float4*)&Es[r][c4*4] = *(const float4*)(g_ek + base);
        *(float4*)&Vs[r][c4*4] = *(const float4*)(g_vv + base);
        __syncthreads();
        #pragma unroll
        for (int kk = 0; kk < 16; kk++) {
            float a[4], v4[4];
            #pragma unroll
            for (int i = 0; i < 4; i++) a[i]  = Es[kk][ty*4 + i];
            #pragma unroll
            for (int j = 0; j < 4; j++) v4[j] = Vs[kk][tx*4 + j];
            #pragma unroll
            for (int i = 0; i < 4; i++)
                #pragma unroll
                for (int j = 0; j < 4; j++) acc[i][j] += a[i] * v4[j];
        }
        __syncthreads();
    }
    float* A = g_attn + (size_t)bh*DH*DH;
    #pragma unroll
    for (int i = 0; i < 4; i++)
        #pragma unroll
        for (int j = 0; j < 4; j++)
            atomicAdd(&A[(ty*4 + i)*DH + tx*4 + j], acc[i][j]);
}

// ---------------- y = q_h @ (attn_h / ksum) ----------------
__global__ __launch_bounds__(256) void y_k() {
    int bh = blockIdx.x; int b = bh >> 3; int h = bh & 7;
    int t0 = b*Tt + blockIdx.y * 128;
    __shared__ float Ah[DH][DH];
    __shared__ float Qs[16][128];
    int tid = threadIdx.x, ty = tid >> 4, tx = tid & 15;
    {
        const float* A  = g_attn + (size_t)bh*DH*DH;
        const float* ks = g_ksum + b*Dd + h*DH;
        #pragma unroll
        for (int i = 0; i < 4; i++) {
            int f = tid + i * 256;
            int d = f >> 4, l4 = f & 15;
            float rk = 1.f / ks[d];
            float4 a = *(const float4*)(A + d*DH + l4*4);
            a.x *= rk; a.y *= rk; a.z *= rk; a.w *= rk;
            *(float4*)&Ah[d][l4*4] = a;
        }
    }
    float acc[8][4] = {};
    for (int k0 = 0; k0 < DH; k0 += 16) {
        #pragma unroll
        for (int i = 0; i < 2; i++) {
            int f = tid + i * 256;
            int r = f >> 2, c4 = f & 3;
            float4 q = *(const float4*)(g_qs + (size_t)(t0 + r)*Dd + h*DH + k0 + c4*4);
            Qs[c4*4+0][r] = q.x; Qs[c4*4+1][r] = q.y;
            Qs[c4*4+2][r] = q.z; Qs[c4*4+3][r] = q.w;
        }
        __syncthreads();
        #pragma unroll
        for (int kk = 0; kk < 16; kk++) {
            float a[8], bb[4];
            #pragma unroll
            for (int i = 0; i < 8; i++) a[i]  = Qs[kk][ty*8 + i];
            #pragma unroll
            for (int j = 0; j < 4; j++) bb[j] = Ah[k0 + kk][tx*4 + j];
            #pragma unroll
            for (int i = 0; i < 8; i++)
                #pragma unroll
                for (int j = 0; j < 4; j++) acc[i][j] += a[i] * bb[j];
        }
        __syncthreads();
    }
    #pragma unroll
    for (int i = 0; i < 8; i++) {
        int tokr = t0 + ty*8 + i;
        float4 o; o.x = acc[i][0]; o.y = acc[i][1]; o.z = acc[i][2]; o.w = acc[i][3];
        *(float4*)(g_y + (size_t)tokr*Dd + h*DH + tx*4) = o;
    }
}

// ---------------- stylize + silu -> g_hs (tf32-rounded) ----------------
__global__ void style_k(const float* __restrict__ g2, const float* __restrict__ b2) {
    int tok = blockIdx.x, tid = threadIdx.x;
    int b = tok >> 13;
    float4 v = ((const float4*)(g_y + (size_t)tok*Dd))[tid];
    float s = v.x + v.y + v.z + v.w;
    __shared__ float r1[4], r2[4];
    for (int o = 16; o; o >>= 1) s += __shfl_xor_sync(0xffffffffu, s, o);
    if ((tid & 31) == 0) r1[tid >> 5] = s;
    __syncthreads();
    float mu = (r1[0] + r1[1] + r1[2] + r1[3]) * (1.f / Dd);
    float a = v.x - mu, bb_ = v.y - mu, c = v.z - mu, d = v.w - mu;
    float ss = a*a + bb_*bb_ + c*c + d*d;
    for (int o = 16; o; o >>= 1) ss += __shfl_xor_sync(0xffffffffu, ss, o);
    if ((tid & 31) == 0) r2[tid >> 5] = ss;
    __syncthreads();
    float var = (r2[0] + r2[1] + r2[2] + r2[3]) * (1.f / Dd);
    float rs = rsqrtf(var + 1e-5f);
    float4 gg = ((const float4*)g2)[tid], bt = ((const float4*)b2)[tid];
    float4 sc = ((const float4*)(g_emb + b*2*Dd))[tid];
    float4 sh = ((const float4*)(g_emb + b*2*Dd + Dd))[tid];
    float h0 = (a  *rs*gg.x + bt.x)*(1.f + sc.x) + sh.x;
    float h1 = (bb_*rs*gg.y + bt.y)*(1.f + sc.y) + sh.y;
    float h2 = (c  *rs*gg.z + bt.z)*(1.f + sc.z) + sh.z;
    float h3 = (d  *rs*gg.w + bt.w)*(1.f + sc.w) + sh.w;
    h0 = h0 / (1.f + expf(-h0));
    h1 = h1 / (1.f + expf(-h1));
    h2 = h2 / (1.f + expf(-h2));
    h3 = h3 / (1.f + expf(-h3));
    float4 o4;
    o4.x = tf32_round(h0); o4.y = tf32_round(h1);
    o4.z = tf32_round(h2); o4.w = tf32_round(h3);
    ((float4*)(g_hs + (size_t)tok*Dd))[tid] = o4;
}

// ---------------- launch ----------------
extern "C" void kernel_launch(void* const* d_in, const int* in_sizes, int n_in,
                              void* d_out, int out_size) {
    const float* x     = (const float*)d_in[0];
    const float* emb   = (const float*)d_in[1];
    const float* mask  = (const float*)d_in[2];
    const float* gamma = (const float*)d_in[3];
    const float* beta  = (const float*)d_in[4];
    const float* Wq    = (const float*)d_in[5];
    const float* bq    = (const float*)d_in[6];
    const float* Wk    = (const float*)d_in[7];
    const float* bk    = (const float*)d_in[8];
    const float* Wv    = (const float*)d_in[9];
    const float* bv    = (const float*)d_in[10];
    const float* embW  = (const float*)d_in[11];
    const float* embB  = (const float*)d_in[12];
    const float* g2    = (const float*)d_in[13];
    const float* b2    = (const float*)d_in[14];
    const float* outW  = (const float*)d_in[15];
    const float* outB  = (const float*)d_in[16];
    float* out = (float*)d_out;

    static int smem_set = 0;
    if (!smem_set) {
        cudaFuncSetAttribute(gemm_k, cudaFuncAttributeMaxDynamicSharedMemorySize, SMEM_BYTES);
        smem_set = 1;
    }

    zero_k <<<512, 256>>>();
    wconv_k<<<dim3(16, 16, 4), dim3(32, 8)>>>(Wq, Wk, Wv, outW);
    emb_k  <<<dim3(Bb, 4), 256>>>(emb, embW, embB);
    ln_k   <<<NTOK, 128>>>(x, gamma, beta);
    gemm_k <<<dim3(12, NTOK/128), 256, SMEM_BYTES>>>(0, bq, bk, bv, mask, nullptr, nullptr);
    kv_k   <<<dim3(Bb*Hh, 16), 256>>>();
    y_k    <<<dim3(Bb*Hh, Tt/128), 256>>>();
    style_k<<<NTOK, 128>>>(g2, b2);
    gemm_k <<<dim3(4, NTOK/128), 256, SMEM_BYTES>>>(1, outB, nullptr, nullptr, nullptr, x, out);
}

// round 4
// speedup vs baseline: 3.3514x; 1.0476x over previous
#include <cuda_runtime.h>
#include <cuda_bf16.h>
#include <math.h>
#include <stdint.h>

#define Bb   4
#define Tt   8192
#define Dd   512
#define Hh   8
#define DH   64
#define TEE  2048
#define NTOK (Bb*Tt)

// ---------------- scratch ----------------
__device__ float g_xn[NTOK*Dd];            // LN(x), tf32-rounded
__device__ float g_hs[NTOK*Dd];            // silu(stylized), tf32-rounded
__device__ float g_qkvT[3*Dd*Dd];          // [1536][512] W^T, tf32-rounded
__device__ float g_outT[Dd*Dd];            // [512][512]  W^T, tf32-rounded
__device__ float g_qs[NTOK*Dd];
__device__ float g_ek[NTOK*Dd];
__device__ float g_vv[NTOK*Dd];
__device__ float g_y [NTOK*Dd];
__device__ float g_ksum[Bb*Dd];
__device__ float g_attn[Bb*Hh*DH*DH];
__device__ float g_emb[Bb*2*Dd];

// ---------------- helpers ----------------
__device__ __forceinline__ float tf32_round(float f) {
    uint32_t u;
    asm("cvt.rna.tf32.f32 %0, %1;" : "=r"(u) : "f"(f));
    return __uint_as_float(u);
}
__device__ __forceinline__ void cp16(void* dst, const void* src) {
    uint32_t d;
    asm("{ .reg .u64 t; cvta.to.shared.u64 t, %1; cvt.u32.u64 %0, t; }" : "=r"(d) : "l"(dst));
    asm volatile("cp.async.cg.shared.global [%0], [%1], 16;" :: "r"(d), "l"(src) : "memory");
}
__device__ __forceinline__ void mma_tf32(float* c, const uint32_t* a, const uint32_t* b) {
    asm volatile(
        "mma.sync.aligned.m16n8k8.row.col.f32.tf32.tf32.f32 "
        "{%0,%1,%2,%3}, {%4,%5,%6,%7}, {%8,%9}, {%0,%1,%2,%3};"
        : "+f"(c[0]), "+f"(c[1]), "+f"(c[2]), "+f"(c[3])
        : "r"(a[0]), "r"(a[1]), "r"(a[2]), "r"(a[3]), "r"(b[0]), "r"(b[1]));
}

// ---------------- zero accumulators ----------------
__global__ void zero_k() {
    int i = blockIdx.x * blockDim.x + threadIdx.x;
    if (i < Bb*Dd) g_ksum[i] = 0.f;
    if (i < Bb*Hh*DH*DH) g_attn[i] = 0.f;
}

// ---------------- weight transpose + tf32 round ----------------
__global__ void wconv_k(const float* __restrict__ Wq, const float* __restrict__ Wk,
                        const float* __restrict__ Wv, const float* __restrict__ Wo) {
    __shared__ float t[32][33];
    int mat = blockIdx.z;
    const float* W = mat == 0 ? Wq : mat == 1 ? Wk : mat == 2 ? Wv : Wo;
    int k0 = blockIdx.y * 32, n0 = blockIdx.x * 32;
    int tx = threadIdx.x, ty = threadIdx.y;
    #pragma unroll
    for (int i = 0; i < 4; i++)
        t[ty + i*8][tx] = W[(size_t)(k0 + ty + i*8)*Dd + n0 + tx];
    __syncthreads();
    float* dst = (mat < 3) ? g_qkvT : g_outT;
    int nbase = (mat < 3) ? mat*Dd : 0;
    #pragma unroll
    for (int i = 0; i < 4; i++) {
        int n = n0 + ty + i*8, k = k0 + tx;
        dst[(size_t)(nbase + n)*Dd + k] = tf32_round(t[tx][ty + i*8]);
    }
}

// ---------------- emb_out = silu(emb) @ emb_W + emb_b ----------------
__global__ void emb_k(const float* __restrict__ emb,
                      const float* __restrict__ W,
                      const float* __restrict__ bias) {
    __shared__ float se[TEE];
    int b = blockIdx.x, tid = threadIdx.x;
    for (int i = tid; i < TEE; i += 256) {
        float e = emb[b*TEE + i];
        se[i] = e / (1.f + __expf(-e));
    }
    __syncthreads();
    int o = blockIdx.y * 256 + tid;
    float acc = bias[o];
    #pragma unroll 4
    for (int e = 0; e < TEE; e++)
        acc += se[e] * W[(size_t)e*(2*Dd) + o];
    g_emb[b*2*Dd + o] = acc;
}

// ---------------- LN(x) -> g_xn (tf32-rounded) ----------------
__global__ void ln_k(const float* __restrict__ x,
                     const float* __restrict__ g,
                     const float* __restrict__ be) {
    int tok = blockIdx.x, tid = threadIdx.x;
    float4 v = ((const float4*)(x + (size_t)tok*Dd))[tid];
    float s = v.x + v.y + v.z + v.w;
    __shared__ float r1[4], r2[4];
    for (int o = 16; o; o >>= 1) s += __shfl_xor_sync(0xffffffffu, s, o);
    if ((tid & 31) == 0) r1[tid >> 5] = s;
    __syncthreads();
    float mu = (r1[0] + r1[1] + r1[2] + r1[3]) * (1.f / Dd);
    float a = v.x - mu, b = v.y - mu, c = v.z - mu, d = v.w - mu;
    float ss = a*a + b*b + c*c + d*d;
    for (int o = 16; o; o >>= 1) ss += __shfl_xor_sync(0xffffffffu, ss, o);
    if ((tid & 31) == 0) r2[tid >> 5] = ss;
    __syncthreads();
    float var = (r2[0] + r2[1] + r2[2] + r2[3]) * (1.f / Dd);
    float rs = rsqrtf(var + 1e-5f);
    float4 gg = ((const float4*)g)[tid], bb = ((const float4*)be)[tid];
    float4 o4;
    o4.x = tf32_round(a*rs*gg.x + bb.x); o4.y = tf32_round(b*rs*gg.y + bb.y);
    o4.z = tf32_round(c*rs*gg.z + bb.z); o4.w = tf32_round(d*rs*gg.w + bb.w);
    ((float4*)(g_xn + (size_t)tok*Dd))[tid] = o4;
}

// ---------------- HMMA tf32 GEMM: BM=256, BN=128, BK=32, warp tile 64x64 -------
#define STG_A (256*36)
#define STG_B (128*36)
#define STAGE_F (STG_A + STG_B)
#define SMEM_BYTES (3*STAGE_F*4)           // 165888 > 256*132*4 = 135168

__device__ __forceinline__ void copy_stage(float* sm, int st, int kc,
    const float* __restrict__ Ag, const float* __restrict__ Bg,
    int m0, int n0, int tid)
{
    float* A = sm + st*STAGE_F;
    float* B = A + STG_A;
    #pragma unroll
    for (int i = 0; i < 8; i++) {
        int s = tid + i*256;
        int r = s >> 3, c8 = s & 7;
        cp16(A + r*36 + c8*4, Ag + (size_t)(m0 + r)*Dd + kc*32 + c8*4);
    }
    #pragma unroll
    for (int i = 0; i < 4; i++) {
        int s = tid + i*256;
        int r = s >> 3, c8 = s & 7;
        cp16(B + r*36 + c8*4, Bg + (size_t)(n0 + r)*Dd + kc*32 + c8*4);
    }
    asm volatile("cp.async.commit_group;" ::: "memory");
}

__global__ __launch_bounds__(256, 1) void gemm_k(
    int mode,                       // 0 = QKV, 1 = OUT
    const float* __restrict__ b0, const float* __restrict__ b1, const float* __restrict__ b2,
    const float* __restrict__ mask, const float* __restrict__ xres, float* __restrict__ outp)
{
    extern __shared__ float sm[];
    int tid = threadIdx.x;
    int lane = tid & 31, w = tid >> 5;
    int g = lane >> 2, cq = lane & 3;
    int wm = w >> 1, wn = w & 1;           // 4 x 2 warps, 64x64 tiles
    int mBase = wm*64, nBase = wn*64;
    int m0 = blockIdx.y * 256;
    int n0 = blockIdx.x * 128;

    const float* Ag = mode ? g_hs : g_xn;
    const float* Bg = mode ? g_outT : g_qkvT;

    float acc[4][8][4];
    #pragma unroll
    for (int i = 0; i < 4; i++)
        #pragma unroll
        for (int j = 0; j < 8; j++)
            #pragma unroll
            for (int r = 0; r < 4; r++) acc[i][j][r] = 0.f;

    copy_stage(sm, 0, 0, Ag, Bg, m0, n0, tid);
    copy_stage(sm, 1, 1, Ag, Bg, m0, n0, tid);

    const int NIT = Dd/32;                 // 16
    for (int it = 0; it < NIT; it++) {
        if (it + 2 < NIT) copy_stage(sm, (it+2)%3, it+2, Ag, Bg, m0, n0, tid);
        if (it + 2 < NIT)      asm volatile("cp.async.wait_group 2;" ::: "memory");
        else if (it + 1 < NIT) asm volatile("cp.async.wait_group 1;" ::: "memory");
        else                   asm volatile("cp.async.wait_group 0;" ::: "memory");
        __syncthreads();

        const uint32_t* As = (const uint32_t*)(sm + (it%3)*STAGE_F);
        const uint32_t* Bs = As + STG_A;
        #pragma unroll
        for (int k8 = 0; k8 < 4; k8++) {
            int kk = k8*8;
            uint32_t a[4][4], b[8][2];
            #pragma unroll
            for (int mt = 0; mt < 4; mt++) {
                int r = mBase + mt*16 + g;
                a[mt][0] = As[r*36 + kk + cq];
                a[mt][1] = As[(r+8)*36 + kk + cq];
                a[mt][2] = As[r*36 + kk + cq + 4];
                a[mt][3] = As[(r+8)*36 + kk + cq + 4];
            }
            #pragma unroll
            for (int nt = 0; nt < 8; nt++) {
                int r = nBase + nt*8 + g;
                b[nt][0] = Bs[r*36 + kk + cq];
                b[nt][1] = Bs[r*36 + kk + cq + 4];
            }
            #pragma unroll
            for (int mt = 0; mt < 4; mt++)
                #pragma unroll
                for (int nt = 0; nt < 8; nt++)
                    mma_tf32(acc[mt][nt], a[mt], b[nt]);
        }
        __syncthreads();
    }

    // stage C tile to shared (reuse pipeline smem)
    float (*Cs)[132] = (float (*)[132])sm;
    #pragma unroll
    for (int mt = 0; mt < 4; mt++) {
        int r = mBase + mt*16 + g;
        #pragma unroll
        for (int nt = 0; nt < 8; nt++) {
            int cc = nBase + nt*8 + cq*2;
            Cs[r][cc]     = acc[mt][nt][0];
            Cs[r][cc+1]   = acc[mt][nt][1];
            Cs[r+8][cc]   = acc[mt][nt][2];
            Cs[r+8][cc+1] = acc[mt][nt][3];
        }
    }
    __syncthreads();

    // epilogue: thread = one row (256 rows), loop over 64-col halves
    int row = tid;
    int m = m0 + row;
    int region = n0 >> 9;
    if (mode == 1) {
        #pragma unroll
        for (int half = 0; half < 2; half++) {
            int ngl = n0 + half*64;
            const float* crow = &Cs[row][half*64];
            #pragma unroll
            for (int j = 0; j < 64; j += 4) {
                size_t off = (size_t)m*Dd + ngl + j;
                float4 xr = *(const float4*)(xres + off);
                float4 o;
                o.x = crow[j]   + b0[ngl+j]   + xr.x;
                o.y = crow[j+1] + b0[ngl+j+1] + xr.y;
                o.z = crow[j+2] + b0[ngl+j+2] + xr.z;
                o.w = crow[j+3] + b0[ngl+j+3] + xr.w;
                *(float4*)(outp + off) = o;
            }
        }
    } else if (region == 0) {
        #pragma unroll
        for (int half = 0; half < 2; half++) {
            int c5 = (n0 & 511) + half*64;
            const float* crow = &Cs[row][half*64];
            float v[64];
            float mx = -1e30f;
            #pragma unroll
            for (int j = 0; j < 64; j++) { v[j] = crow[j] + b0[c5+j]; mx = fmaxf(mx, v[j]); }
            float s = 0.f;
            #pragma unroll
            for (int j = 0; j < 64; j++) { v[j] = __expf(v[j] - mx); s += v[j]; }
            float inv = 1.f / s;
            #pragma unroll
            for (int j = 0; j < 64; j += 4) {
                float4 o; o.x = v[j]*inv; o.y = v[j+1]*inv; o.z = v[j+2]*inv; o.w = v[j+3]*inv;
                *(float4*)(g_qs + (size_t)m*Dd + c5 + j) = o;
            }
        }
    } else if (region == 1) {
        float madd = (1.f - mask[m]) * (-1e6f);
        #pragma unroll
        for (int half = 0; half < 2; half++) {
            int c5 = (n0 & 511) + half*64;
            float* crow = &Cs[row][half*64];
            float v[64];
            #pragma unroll
            for (int j = 0; j < 64; j++) v[j] = __expf(crow[j] + b1[c5+j] + madd);
            #pragma unroll
            for (int j = 0; j < 64; j += 4) {
                float4 o; o.x = v[j]; o.y = v[j+1]; o.z = v[j+2]; o.w = v[j+3];
                *(float4*)(g_ek + (size_t)m*Dd + c5 + j) = o;
            }
            #pragma unroll
            for (int j = 0; j < 64; j++) crow[j] = v[j];   // for column sums
        }
        __syncthreads();
        if (tid < 128) {
            float s = 0.f;
            #pragma unroll 8
            for (int r = 0; r < 256; r++) s += Cs[r][tid];
            atomicAdd(&g_ksum[(m0 >> 13)*Dd + (n0 & 511) + tid], s);
        }
    } else {
        float mv = mask[m];
        #pragma unroll
        for (int half = 0; half < 2; half++) {
            int c5 = (n0 & 511) + half*64;
            const float* crow = &Cs[row][half*64];
            #pragma unroll
            for (int j = 0; j < 64; j += 4) {
                float4 o;
                o.x = (crow[j]   + b2[c5+j]  ) * mv;
                o.y = (crow[j+1] + b2[c5+j+1]) * mv;
                o.z = (crow[j+2] + b2[c5+j+2]) * mv;
                o.w = (crow[j+3] + b2[c5+j+3]) * mv;
                *(float4*)(g_vv + (size_t)m*Dd + c5 + j) = o;
            }
        }
    }
}

// ---------------- KV state (tensor): attn[b,h] += ek^T @ vv over 512-token chunks
__global__ __launch_bounds__(128) void kv_k() {
    __shared__ float Es[64][72];
    __shared__ float Vs[64][72];
    int bh = blockIdx.x; int b = bh >> 3; int h = bh & 7;
    int t0 = b*Tt + blockIdx.y * 512;
    int tid = threadIdx.x;
    int lane = tid & 31, w = tid >> 5;
    int g = lane >> 2, cq = lane & 3;
    int mBase = w * 16;                     // d-rows per warp

    float acc[8][4];
    #pragma unroll
    for (int i = 0; i < 8; i++)
        #pragma unroll
        for (int r = 0; r < 4; r++) acc[i][r] = 0.f;

    for (int tile = 0; tile < 8; tile++) {
        #pragma unroll
        for (int i = 0; i < 8; i++) {
            int s = tid + i*128;
            int r = s >> 4, c4 = s & 15;
            size_t base = (size_t)(t0 + tile*64 + r)*Dd + h*DH + c4*4;
            *(float4*)&Es[r][c4*4] = *(const float4*)(g_ek + base);
            *(float4*)&Vs[r][c4*4] = *(const float4*)(g_vv + base);
        }
        __syncthreads();
        #pragma unroll
        for (int k8 = 0; k8 < 8; k8++) {
            int kk = k8*8;
            uint32_t a[4], bfr[8][2];
            a[0] = __float_as_uint(Es[kk+cq][mBase+g]);
            a[1] = __float_as_uint(Es[kk+cq][mBase+g+8]);
            a[2] = __float_as_uint(Es[kk+cq+4][mBase+g]);
            a[3] = __float_as_uint(Es[kk+cq+4][mBase+g+8]);
            #pragma unroll
            for (int nt = 0; nt < 8; nt++) {
                bfr[nt][0] = __float_as_uint(Vs[kk+cq][nt*8+g]);
                bfr[nt][1] = __float_as_uint(Vs[kk+cq+4][nt*8+g]);
            }
            #pragma unroll
            for (int nt = 0; nt < 8; nt++)
                mma_tf32(acc[nt], a, bfr[nt]);
        }
        __syncthreads();
    }
    float* A = g_attn + (size_t)bh*DH*DH;
    #pragma unroll
    for (int nt = 0; nt < 8; nt++) {
        int n = nt*8 + cq*2;
        atomicAdd(&A[(mBase+g)*DH + n],     acc[nt][0]);
        atomicAdd(&A[(mBase+g)*DH + n+1],   acc[nt][1]);
        atomicAdd(&A[(mBase+g+8)*DH + n],   acc[nt][2]);
        atomicAdd(&A[(mBase+g+8)*DH + n+1], acc[nt][3]);
    }
}

// ---------------- y = q_h @ (attn_h / ksum)  (tensor) ----------------
__global__ __launch_bounds__(128) void y_k() {
    __shared__ float Qs[64][68];
    __shared__ float Ahs[64][72];
    int bh = blockIdx.x; int b = bh >> 3; int h = bh & 7;
    int t0 = b*Tt + blockIdx.y * 64;
    int tid = threadIdx.x;
    int lane = tid & 31, w = tid >> 5;
    int g = lane >> 2, cq = lane & 3;
    int mBase = w * 16;                     // token rows per warp

    {
        const float* A  = g_attn + (size_t)bh*DH*DH;
        const float* ks = g_ksum + b*Dd + h*DH;
        #pragma unroll
        for (int i = 0; i < 8; i++) {
            int s = tid + i*128;
            int r = s >> 4, c4 = s & 15;
            float rk = 1.f / ks[r];
            float4 a = *(const float4*)(A + r*DH + c4*4);
            a.x *= rk; a.y *= rk; a.z *= rk; a.w *= rk;
            *(float4*)&Ahs[r][c4*4] = a;
            *(float4*)&Qs[r][c4*4] = *(const float4*)(g_qs + (size_t)(t0 + r)*Dd + h*DH + c4*4);
        }
    }
    __syncthreads();

    float acc[8][4];
    #pragma unroll
    for (int i = 0; i < 8; i++)
        #pragma unroll
        for (int r = 0; r < 4; r++) acc[i][r] = 0.f;

    #pragma unroll
    for (int k8 = 0; k8 < 8; k8++) {
        int kk = k8*8;
        uint32_t a[4], bfr[8][2];
        a[0] = __float_as_uint(Qs[mBase+g][kk+cq]);
        a[1] = __float_as_uint(Qs[mBase+g+8][kk+cq]);
        a[2] = __float_as_uint(Qs[mBase+g][kk+cq+4]);
        a[3] = __float_as_uint(Qs[mBase+g+8][kk+cq+4]);
        #pragma unroll
        for (int nt = 0; nt < 8; nt++) {
            bfr[nt][0] = __float_as_uint(Ahs[kk+cq][nt*8+g]);
            bfr[nt][1] = __float_as_uint(Ahs[kk+cq+4][nt*8+g]);
        }
        #pragma unroll
        for (int nt = 0; nt < 8; nt++)
            mma_tf32(acc[nt], a, bfr[nt]);
    }

    #pragma unroll
    for (int nt = 0; nt < 8; nt++) {
        int n = h*DH + nt*8 + cq*2;
        size_t r0 = (size_t)(t0 + mBase + g)*Dd + n;
        size_t r1 = (size_t)(t0 + mBase + g + 8)*Dd + n;
        *(float2*)(g_y + r0) = make_float2(acc[nt][0], acc[nt][1]);
        *(float2*)(g_y + r1) = make_float2(acc[nt][2], acc[nt][3]);
    }
}

// ---------------- stylize + silu -> g_hs (tf32-rounded) ----------------
__global__ void style_k(const float* __restrict__ g2, const float* __restrict__ b2) {
    int tok = blockIdx.x, tid = threadIdx.x;
    int b = tok >> 13;
    float4 v = ((const float4*)(g_y + (size_t)tok*Dd))[tid];
    float s = v.x + v.y + v.z + v.w;
    __shared__ float r1[4], r2[4];
    for (int o = 16; o; o >>= 1) s += __shfl_xor_sync(0xffffffffu, s, o);
    if ((tid & 31) == 0) r1[tid >> 5] = s;
    __syncthreads();
    float mu = (r1[0] + r1[1] + r1[2] + r1[3]) * (1.f / Dd);
    float a = v.x - mu, bb_ = v.y - mu, c = v.z - mu, d = v.w - mu;
    float ss = a*a + bb_*bb_ + c*c + d*d;
    for (int o = 16; o; o >>= 1) ss += __shfl_xor_sync(0xffffffffu, ss, o);
    if ((tid & 31) == 0) r2[tid >> 5] = ss;
    __syncthreads();
    float var = (r2[0] + r2[1] + r2[2] + r2[3]) * (1.f / Dd);
    float rs = rsqrtf(var + 1e-5f);
    float4 gg = ((const float4*)g2)[tid], bt = ((const float4*)b2)[tid];
    float4 sc = ((const float4*)(g_emb + b*2*Dd))[tid];
    float4 sh = ((const float4*)(g_emb + b*2*Dd + Dd))[tid];
    float h0 = (a  *rs*gg.x + bt.x)*(1.f + sc.x) + sh.x;
    float h1 = (bb_*rs*gg.y + bt.y)*(1.f + sc.y) + sh.y;
    float h2 = (c  *rs*gg.z + bt.z)*(1.f + sc.z) + sh.z;
    float h3 = (d  *rs*gg.w + bt.w)*(1.f + sc.w) + sh.w;
    h0 = h0 / (1.f + __expf(-h0));
    h1 = h1 / (1.f + __expf(-h1));
    h2 = h2 / (1.f + __expf(-h2));
    h3 = h3 / (1.f + __expf(-h3));
    float4 o4;
    o4.x = tf32_round(h0); o4.y = tf32_round(h1);
    o4.z = tf32_round(h2); o4.w = tf32_round(h3);
    ((float4*)(g_hs + (size_t)tok*Dd))[tid] = o4;
}

// ---------------- launch ----------------
extern "C" void kernel_launch(void* const* d_in, const int* in_sizes, int n_in,
                              void* d_out, int out_size) {
    const float* x     = (const float*)d_in[0];
    const float* emb   = (const float*)d_in[1];
    const float* mask  = (const float*)d_in[2];
    const float* gamma = (const float*)d_in[3];
    const float* beta  = (const float*)d_in[4];
    const float* Wq    = (const float*)d_in[5];
    const float* bq    = (const float*)d_in[6];
    const float* Wk    = (const float*)d_in[7];
    const float* bk    = (const float*)d_in[8];
    const float* Wv    = (const float*)d_in[9];
    const float* bv    = (const float*)d_in[10];
    const float* embW  = (const float*)d_in[11];
    const float* embB  = (const float*)d_in[12];
    const float* g2    = (const float*)d_in[13];
    const float* b2    = (const float*)d_in[14];
    const float* outW  = (const float*)d_in[15];
    const float* outB  = (const float*)d_in[16];
    float* out = (float*)d_out;

    static int smem_set = 0;
    if (!smem_set) {
        cudaFuncSetAttribute(gemm_k, cudaFuncAttributeMaxDynamicSharedMemorySize, SMEM_BYTES);
        smem_set = 1;
    }

    zero_k <<<512, 256>>>();
    wconv_k<<<dim3(16, 16, 4), dim3(32, 8)>>>(Wq, Wk, Wv, outW);
    emb_k  <<<dim3(Bb, 4), 256>>>(emb, embW, embB);
    ln_k   <<<NTOK, 128>>>(x, gamma, beta);
    gemm_k <<<dim3(12, NTOK/256), 256, SMEM_BYTES>>>(0, bq, bk, bv, mask, nullptr, nullptr);
    kv_k   <<<dim3(Bb*Hh, 16), 128>>>();
    y_k    <<<dim3(Bb*Hh, Tt/64), 128>>>();
    style_k<<<NTOK, 128>>>(g2, b2);
    gemm_k <<<dim3(4, NTOK/256), 256, SMEM_BYTES>>>(1, outB, nullptr, nullptr, nullptr, x, out);
}

// round 5
// speedup vs baseline: 5.7349x; 1.7112x over previous
#include <cuda_runtime.h>
#include <cuda_fp16.h>
#include <math.h>
#include <stdint.h>

#define Bb   4
#define Tt   8192
#define Dd   512
#define Hh   8
#define DH   64
#define TEE  2048
#define NTOK (Bb*Tt)

// ---------------- scratch ----------------
__device__ __half g_xn[NTOK*Dd];           // LN(x), fp16
__device__ __half g_hs[NTOK*Dd];           // silu(stylized), fp16
__device__ __half g_qkvT[3*Dd*Dd];         // [1536][512] W^T fp16
__device__ __half g_outT[Dd*Dd];           // [512][512]  W^T fp16
__device__ float g_qs[NTOK*Dd];
__device__ float g_ek[NTOK*Dd];
__device__ float g_vv[NTOK*Dd];
__device__ float g_y [NTOK*Dd];
__device__ float g_ksum[Bb*Dd];
__device__ float g_attn[Bb*Hh*DH*DH];
__device__ float g_emb[Bb*2*Dd];

// ---------------- helpers ----------------
__device__ __forceinline__ void cp16(void* dst, const void* src) {
    uint32_t d;
    asm("{ .reg .u64 t; cvta.to.shared.u64 t, %1; cvt.u32.u64 %0, t; }" : "=r"(d) : "l"(dst));
    asm volatile("cp.async.cg.shared.global [%0], [%1], 16;" :: "r"(d), "l"(src) : "memory");
}
__device__ __forceinline__ void mma_f16(float* c, const uint32_t* a, const uint32_t* b) {
    asm volatile(
        "mma.sync.aligned.m16n8k16.row.col.f32.f16.f16.f32 "
        "{%0,%1,%2,%3}, {%4,%5,%6,%7}, {%8,%9}, {%0,%1,%2,%3};"
        : "+f"(c[0]), "+f"(c[1]), "+f"(c[2]), "+f"(c[3])
        : "r"(a[0]), "r"(a[1]), "r"(a[2]), "r"(a[3]), "r"(b[0]), "r"(b[1]));
}
__device__ __forceinline__ void mma_tf32(float* c, const uint32_t* a, const uint32_t* b) {
    asm volatile(
        "mma.sync.aligned.m16n8k8.row.col.f32.tf32.tf32.f32 "
        "{%0,%1,%2,%3}, {%4,%5,%6,%7}, {%8,%9}, {%0,%1,%2,%3};"
        : "+f"(c[0]), "+f"(c[1]), "+f"(c[2]), "+f"(c[3])
        : "r"(a[0]), "r"(a[1]), "r"(a[2]), "r"(a[3]), "r"(b[0]), "r"(b[1]));
}

// ---------------- zero accumulators + seed emb with bias ----------------
__global__ void zero_k(const float* __restrict__ embB) {
    int i = blockIdx.x * blockDim.x + threadIdx.x;
    if (i < Bb*Dd) g_ksum[i] = 0.f;
    if (i < Bb*Hh*DH*DH) g_attn[i] = 0.f;
    if (i < Bb*2*Dd) g_emb[i] = embB[i & (2*Dd - 1)];
}

// ---------------- weight transpose + fp16 ----------------
__global__ void wconv_k(const float* __restrict__ Wq, const float* __restrict__ Wk,
                        const float* __restrict__ Wv, const float* __restrict__ Wo) {
    __shared__ float t[32][33];
    int mat = blockIdx.z;
    const float* W = mat == 0 ? Wq : mat == 1 ? Wk : mat == 2 ? Wv : Wo;
    int k0 = blockIdx.y * 32, n0 = blockIdx.x * 32;
    int tx = threadIdx.x, ty = threadIdx.y;
    #pragma unroll
    for (int i = 0; i < 4; i++)
        t[ty + i*8][tx] = W[(size_t)(k0 + ty + i*8)*Dd + n0 + tx];
    __syncthreads();
    __half* dst = (mat < 3) ? g_qkvT : g_outT;
    int nbase = (mat < 3) ? mat*Dd : 0;
    #pragma unroll
    for (int i = 0; i < 4; i++) {
        int n = n0 + ty + i*8, k = k0 + tx;
        dst[(size_t)(nbase + n)*Dd + k] = __float2half_rn(t[tx][ty + i*8]);
    }
}

// ---------------- emb partial: silu(emb_chunk) @ W_chunk, atomic add ----------
__global__ void emb_k(const float* __restrict__ emb,
                      const float* __restrict__ W) {
    __shared__ float se[256];
    int b = blockIdx.x, oc = blockIdx.y, ec = blockIdx.z;
    int tid = threadIdx.x;
    if (tid < 128) {
        #pragma unroll
        for (int i = 0; i < 2; i++) {
            float e = emb[b*TEE + ec*256 + tid*2 + i];
            se[tid*2 + i] = e / (1.f + __expf(-e));
        }
    }
    __syncthreads();
    int o = oc*128 + (tid & 127);
    int eh = (tid >> 7) * 128;              // 256 threads: two halves of e-range
    float acc = 0.f;
    #pragma unroll 4
    for (int e = 0; e < 128; e++)
        acc += se[eh + e] * W[(size_t)(ec*256 + eh + e)*(2*Dd) + o];
    atomicAdd(&g_emb[b*2*Dd + o], acc);
}

// ---------------- LN(x) -> g_xn (fp16) ----------------
__global__ void ln_k(const float* __restrict__ x,
                     const float* __restrict__ g,
                     const float* __restrict__ be) {
    int tok = blockIdx.x, tid = threadIdx.x;
    float4 v = ((const float4*)(x + (size_t)tok*Dd))[tid];
    float s = v.x + v.y + v.z + v.w;
    __shared__ float r1[4], r2[4];
    for (int o = 16; o; o >>= 1) s += __shfl_xor_sync(0xffffffffu, s, o);
    if ((tid & 31) == 0) r1[tid >> 5] = s;
    __syncthreads();
    float mu = (r1[0] + r1[1] + r1[2] + r1[3]) * (1.f / Dd);
    float a = v.x - mu, b = v.y - mu, c = v.z - mu, d = v.w - mu;
    float ss = a*a + b*b + c*c + d*d;
    for (int o = 16; o; o >>= 1) ss += __shfl_xor_sync(0xffffffffu, ss, o);
    if ((tid & 31) == 0) r2[tid >> 5] = ss;
    __syncthreads();
    float var = (r2[0] + r2[1] + r2[2] + r2[3]) * (1.f / Dd);
    float rs = rsqrtf(var + 1e-5f);
    float4 gg = ((const float4*)g)[tid], bb = ((const float4*)be)[tid];
    __half2* ph = (__half2*)(g_xn + (size_t)tok*Dd);
    ph[tid*2]   = __halves2half2(__float2half_rn(a*rs*gg.x + bb.x),
                                 __float2half_rn(b*rs*gg.y + bb.y));
    ph[tid*2+1] = __halves2half2(__float2half_rn(c*rs*gg.z + bb.z),
                                 __float2half_rn(d*rs*gg.w + bb.w));
}

// ---------------- fp16 HMMA GEMM: BM=256, BN=128, BK=32, warp tile 64x64 -------
#define AROW 40                            // halves per smem row (pad 32->40)
#define STG_A (256*AROW)                   // halves
#define STG_B (128*AROW)
#define STAGE_H (STG_A + STG_B)            // 15360 halves = 30720 B
#define SMEM_BYTES (256*132*4)             // C staging dominates (135168 > 3*30720)

__device__ __forceinline__ void copy_stage(__half* smh, int st, int kc,
    const __half* __restrict__ Ag, const __half* __restrict__ Bg,
    int m0, int n0, int tid)
{
    __half* A = smh + st*STAGE_H;
    __half* B = A + STG_A;
    #pragma unroll
    for (int i = 0; i < 4; i++) {           // A: 256 rows x 4 chunks of 8 halves
        int s = tid + i*256;
        int r = s >> 2, c8 = s & 3;
        cp16(A + r*AROW + c8*8, Ag + (size_t)(m0 + r)*Dd + kc*32 + c8*8);
    }
    #pragma unroll
    for (int i = 0; i < 2; i++) {           // B: 128 rows x 4 chunks
        int s = tid + i*256;
        int r = s >> 2, c8 = s & 3;
        cp16(B + r*AROW + c8*8, Bg + (size_t)(n0 + r)*Dd + kc*32 + c8*8);
    }
    asm volatile("cp.async.commit_group;" ::: "memory");
}

__global__ __launch_bounds__(256, 1) void gemm_k(
    int mode,                       // 0 = QKV, 1 = OUT
    const float* __restrict__ b0, const float* __restrict__ b1, const float* __restrict__ b2,
    const float* __restrict__ mask, const float* __restrict__ xres, float* __restrict__ outp)
{
    extern __shared__ __half smh[];
    int tid = threadIdx.x;
    int lane = tid & 31, w = tid >> 5;
    int g = lane >> 2, cq = lane & 3;
    int wm = w >> 1, wn = w & 1;           // 4 x 2 warps, 64x64 tiles
    int mBase = wm*64, nBase = wn*64;
    int m0 = blockIdx.y * 256;
    int n0 = blockIdx.x * 128;

    const __half* Ag = mode ? g_hs : g_xn;
    const __half* Bg = mode ? g_outT : g_qkvT;

    float acc[4][8][4];
    #pragma unroll
    for (int i = 0; i < 4; i++)
        #pragma unroll
        for (int j = 0; j < 8; j++)
            #pragma unroll
            for (int r = 0; r < 4; r++) acc[i][j][r] = 0.f;

    copy_stage(smh, 0, 0, Ag, Bg, m0, n0, tid);
    copy_stage(smh, 1, 1, Ag, Bg, m0, n0, tid);

    const int NIT = Dd/32;                 // 16
    for (int it = 0; it < NIT; it++) {
        if (it + 2 < NIT) copy_stage(smh, (it+2)%3, it+2, Ag, Bg, m0, n0, tid);
        if (it + 2 < NIT)      asm volatile("cp.async.wait_group 2;" ::: "memory");
        else if (it + 1 < NIT) asm volatile("cp.async.wait_group 1;" ::: "memory");
        else                   asm volatile("cp.async.wait_group 0;" ::: "memory");
        __syncthreads();

        const __half* As = smh + (it%3)*STAGE_H;
        const __half* Bs = As + STG_A;
        #pragma unroll
        for (int k16 = 0; k16 < 2; k16++) {
            int kh = k16*16;
            uint32_t a[4][4], b[8][2];
            #pragma unroll
            for (int mt = 0; mt < 4; mt++) {
                int r = mBase + mt*16 + g;
                a[mt][0] = *(const uint32_t*)(As + r*AROW + kh + 2*cq);
                a[mt][1] = *(const uint32_t*)(As + (r+8)*AROW + kh + 2*cq);
                a[mt][2] = *(const uint32_t*)(As + r*AROW + kh + 2*cq + 8);
                a[mt][3] = *(const uint32_t*)(As + (r+8)*AROW + kh + 2*cq + 8);
            }
            #pragma unroll
            for (int nt = 0; nt < 8; nt++) {
                int r = nBase + nt*8 + g;
                b[nt][0] = *(const uint32_t*)(Bs + r*AROW + kh + 2*cq);
                b[nt][1] = *(const uint32_t*)(Bs + r*AROW + kh + 2*cq + 8);
            }
            #pragma unroll
            for (int mt = 0; mt < 4; mt++)
                #pragma unroll
                for (int nt = 0; nt < 8; nt++)
                    mma_f16(acc[mt][nt], a[mt], b[nt]);
        }
        __syncthreads();
    }

    // stage C tile to shared (reuse pipeline smem)
    float (*Cs)[132] = (float (*)[132])smh;
    #pragma unroll
    for (int mt = 0; mt < 4; mt++) {
        int r = mBase + mt*16 + g;
        #pragma unroll
        for (int nt = 0; nt < 8; nt++) {
            int cc = nBase + nt*8 + cq*2;
            Cs[r][cc]     = acc[mt][nt][0];
            Cs[r][cc+1]   = acc[mt][nt][1];
            Cs[r+8][cc]   = acc[mt][nt][2];
            Cs[r+8][cc+1] = acc[mt][nt][3];
        }
    }
    __syncthreads();

    // epilogue: thread = one row (256 rows), loop over 64-col halves
    int row = tid;
    int m = m0 + row;
    int region = n0 >> 9;
    if (mode == 1) {
        #pragma unroll
        for (int half = 0; half < 2; half++) {
            int ngl = n0 + half*64;
            const float* crow = &Cs[row][half*64];
            #pragma unroll
            for (int j = 0; j < 64; j += 4) {
                size_t off = (size_t)m*Dd + ngl + j;
                float4 xr = *(const float4*)(xres + off);
                float4 o;
                o.x = crow[j]   + b0[ngl+j]   + xr.x;
                o.y = crow[j+1] + b0[ngl+j+1] + xr.y;
                o.z = crow[j+2] + b0[ngl+j+2] + xr.z;
                o.w = crow[j+3] + b0[ngl+j+3] + xr.w;
                *(float4*)(outp + off) = o;
            }
        }
    } else if (region == 0) {
        #pragma unroll
        for (int half = 0; half < 2; half++) {
            int c5 = (n0 & 511) + half*64;
            const float* crow = &Cs[row][half*64];
            float v[64];
            float mx = -1e30f;
            #pragma unroll
            for (int j = 0; j < 64; j++) { v[j] = crow[j] + b0[c5+j]; mx = fmaxf(mx, v[j]); }
            float s = 0.f;
            #pragma unroll
            for (int j = 0; j < 64; j++) { v[j] = __expf(v[j] - mx); s += v[j]; }
            float inv = 1.f / s;
            #pragma unroll
            for (int j = 0; j < 64; j += 4) {
                float4 o; o.x = v[j]*inv; o.y = v[j+1]*inv; o.z = v[j+2]*inv; o.w = v[j+3]*inv;
                *(float4*)(g_qs + (size_t)m*Dd + c5 + j) = o;
            }
        }
    } else if (region == 1) {
        float madd = (1.f - mask[m]) * (-1e6f);
        #pragma unroll
        for (int half = 0; half < 2; half++) {
            int c5 = (n0 & 511) + half*64;
            float* crow = &Cs[row][half*64];
            float v[64];
            #pragma unroll
            for (int j = 0; j < 64; j++) v[j] = __expf(crow[j] + b1[c5+j] + madd);
            #pragma unroll
            for (int j = 0; j < 64; j += 4) {
                float4 o; o.x = v[j]; o.y = v[j+1]; o.z = v[j+2]; o.w = v[j+3];
                *(float4*)(g_ek + (size_t)m*Dd + c5 + j) = o;
            }
            #pragma unroll
            for (int j = 0; j < 64; j++) crow[j] = v[j];   // for column sums
        }
        __syncthreads();
        if (tid < 128) {
            float s = 0.f;
            #pragma unroll 8
            for (int r = 0; r < 256; r++) s += Cs[r][tid];
            atomicAdd(&g_ksum[(m0 >> 13)*Dd + (n0 & 511) + tid], s);
        }
    } else {
        float mv = mask[m];
        #pragma unroll
        for (int half = 0; half < 2; half++) {
            int c5 = (n0 & 511) + half*64;
            const float* crow = &Cs[row][half*64];
            #pragma unroll
            for (int j = 0; j < 64; j += 4) {
                float4 o;
                o.x = (crow[j]   + b2[c5+j]  ) * mv;
                o.y = (crow[j+1] + b2[c5+j+1]) * mv;
                o.z = (crow[j+2] + b2[c5+j+2]) * mv;
                o.w = (crow[j+3] + b2[c5+j+3]) * mv;
                *(float4*)(g_vv + (size_t)m*Dd + c5 + j) = o;
            }
        }
    }
}

// ---------------- KV state (tf32 tensor) ----------------
__global__ __launch_bounds__(128) void kv_k() {
    __shared__ float Es[64][72];
    __shared__ float Vs[64][72];
    int bh = blockIdx.x; int b = bh >> 3; int h = bh & 7;
    int t0 = b*Tt + blockIdx.y * 512;
    int tid = threadIdx.x;
    int lane = tid & 31, w = tid >> 5;
    int g = lane >> 2, cq = lane & 3;
    int mBase = w * 16;

    float acc[8][4];
    #pragma unroll
    for (int i = 0; i < 8; i++)
        #pragma unroll
        for (int r = 0; r < 4; r++) acc[i][r] = 0.f;

    for (int tile = 0; tile < 8; tile++) {
        #pragma unroll
        for (int i = 0; i < 8; i++) {
            int s = tid + i*128;
            int r = s >> 4, c4 = s & 15;
            size_t base = (size_t)(t0 + tile*64 + r)*Dd + h*DH + c4*4;
            *(float4*)&Es[r][c4*4] = *(const float4*)(g_ek + base);
            *(float4*)&Vs[r][c4*4] = *(const float4*)(g_vv + base);
        }
        __syncthreads();
        #pragma unroll
        for (int k8 = 0; k8 < 8; k8++) {
            int kk = k8*8;
            uint32_t a[4], bfr[8][2];
            a[0] = __float_as_uint(Es[kk+cq][mBase+g]);
            a[1] = __float_as_uint(Es[kk+cq][mBase+g+8]);
            a[2] = __float_as_uint(Es[kk+cq+4][mBase+g]);
            a[3] = __float_as_uint(Es[kk+cq+4][mBase+g+8]);
            #pragma unroll
            for (int nt = 0; nt < 8; nt++) {
                bfr[nt][0] = __float_as_uint(Vs[kk+cq][nt*8+g]);
                bfr[nt][1] = __float_as_uint(Vs[kk+cq+4][nt*8+g]);
            }
            #pragma unroll
            for (int nt = 0; nt < 8; nt++)
                mma_tf32(acc[nt], a, bfr[nt]);
        }
        __syncthreads();
    }
    float* A = g_attn + (size_t)bh*DH*DH;
    #pragma unroll
    for (int nt = 0; nt < 8; nt++) {
        int n = nt*8 + cq*2;
        atomicAdd(&A[(mBase+g)*DH + n],     acc[nt][0]);
        atomicAdd(&A[(mBase+g)*DH + n+1],   acc[nt][1]);
        atomicAdd(&A[(mBase+g+8)*DH + n],   acc[nt][2]);
        atomicAdd(&A[(mBase+g+8)*DH + n+1], acc[nt][3]);
    }
}

// ---------------- y = q_h @ (attn_h / ksum) (tf32 tensor) ----------------
__global__ __launch_bounds__(128) void y_k() {
    __shared__ float Qs[64][68];
    __shared__ float Ahs[64][72];
    int bh = blockIdx.x; int b = bh >> 3; int h = bh & 7;
    int t0 = b*Tt + blockIdx.y * 64;
    int tid = threadIdx.x;
    int lane = tid & 31, w = tid >> 5;
    int g = lane >> 2, cq = lane & 3;
    int mBase = w * 16;

    {
        const float* A  = g_attn + (size_t)bh*DH*DH;
        const float* ks = g_ksum + b*Dd + h*DH;
        #pragma unroll
        for (int i = 0; i < 8; i++) {
            int s = tid + i*128;
            int r = s >> 4, c4 = s & 15;
            float rk = 1.f / ks[r];
            float4 a = *(const float4*)(A + r*DH + c4*4);
            a.x *= rk; a.y *= rk; a.z *= rk; a.w *= rk;
            *(float4*)&Ahs[r][c4*4] = a;
            *(float4*)&Qs[r][c4*4] = *(const float4*)(g_qs + (size_t)(t0 + r)*Dd + h*DH + c4*4);
        }
    }
    __syncthreads();

    float acc[8][4];
    #pragma unroll
    for (int i = 0; i < 8; i++)
        #pragma unroll
        for (int r = 0; r < 4; r++) acc[i][r] = 0.f;

    #pragma unroll
    for (int k8 = 0; k8 < 8; k8++) {
        int kk = k8*8;
        uint32_t a[4], bfr[8][2];
        a[0] = __float_as_uint(Qs[mBase+g][kk+cq]);
        a[1] = __float_as_uint(Qs[mBase+g+8][kk+cq]);
        a[2] = __float_as_uint(Qs[mBase+g][kk+cq+4]);
        a[3] = __float_as_uint(Qs[mBase+g+8][kk+cq+4]);
        #pragma unroll
        for (int nt = 0; nt < 8; nt++) {
            bfr[nt][0] = __float_as_uint(Ahs[kk+cq][nt*8+g]);
            bfr[nt][1] = __float_as_uint(Ahs[kk+cq+4][nt*8+g]);
        }
        #pragma unroll
        for (int nt = 0; nt < 8; nt++)
            mma_tf32(acc[nt], a, bfr[nt]);
    }

    #pragma unroll
    for (int nt = 0; nt < 8; nt++) {
        int n = h*DH + nt*8 + cq*2;
        size_t r0 = (size_t)(t0 + mBase + g)*Dd + n;
        size_t r1 = (size_t)(t0 + mBase + g + 8)*Dd + n;
        *(float2*)(g_y + r0) = make_float2(acc[nt][0], acc[nt][1]);
        *(float2*)(g_y + r1) = make_float2(acc[nt][2], acc[nt][3]);
    }
}

// ---------------- stylize + silu -> g_hs (fp16) ----------------
__global__ void style_k(const float* __restrict__ g2, const float* __restrict__ b2) {
    int tok = blockIdx.x, tid = threadIdx.x;
    int b = tok >> 13;
    float4 v = ((const float4*)(g_y + (size_t)tok*Dd))[tid];
    float s = v.x + v.y + v.z + v.w;
    __shared__ float r1[4], r2[4];
    for (int o = 16; o; o >>= 1) s += __shfl_xor_sync(0xffffffffu, s, o);
    if ((tid & 31) == 0) r1[tid >> 5] = s;
    __syncthreads();
    float mu = (r1[0] + r1[1] + r1[2] + r1[3]) * (1.f / Dd);
    float a = v.x - mu, bb_ = v.y - mu, c = v.z - mu, d = v.w - mu;
    float ss = a*a + bb_*bb_ + c*c + d*d;
    for (int o = 16; o; o >>= 1) ss += __shfl_xor_sync(0xffffffffu, ss, o);
    if ((tid & 31) == 0) r2[tid >> 5] = ss;
    __syncthreads();
    float var = (r2[0] + r2[1] + r2[2] + r2[3]) * (1.f / Dd);
    float rs = rsqrtf(var + 1e-5f);
    float4 gg = ((const float4*)g2)[tid], bt = ((const float4*)b2)[tid];
    float4 sc = ((const float4*)(g_emb + b*2*Dd))[tid];
    float4 sh = ((const float4*)(g_emb + b*2*Dd + Dd))[tid];
    float h0 = (a  *rs*gg.x + bt.x)*(1.f + sc.x) + sh.x;
    float h1 = (bb_*rs*gg.y + bt.y)*(1.f + sc.y) + sh.y;
    float h2 = (c  *rs*gg.z + bt.z)*(1.f + sc.z) + sh.z;
    float h3 = (d  *rs*gg.w + bt.w)*(1.f + sc.w) + sh.w;
    h0 = h0 / (1.f + __expf(-h0));
    h1 = h1 / (1.f + __expf(-h1));
    h2 = h2 / (1.f + __expf(-h2));
    h3 = h3 / (1.f + __expf(-h3));
    __half2* ph = (__half2*)(g_hs + (size_t)tok*Dd);
    ph[tid*2]   = __halves2half2(__float2half_rn(h0), __float2half_rn(h1));
    ph[tid*2+1] = __halves2half2(__float2half_rn(h2), __float2half_rn(h3));
}

// ---------------- launch ----------------
extern "C" void kernel_launch(void* const* d_in, const int* in_sizes, int n_in,
                              void* d_out, int out_size) {
    const float* x     = (const float*)d_in[0];
    const float* emb   = (const float*)d_in[1];
    const float* mask  = (const float*)d_in[2];
    const float* gamma = (const float*)d_in[3];
    const float* beta  = (const float*)d_in[4];
    const float* Wq    = (const float*)d_in[5];
    const float* bq    = (const float*)d_in[6];
    const float* Wk    = (const float*)d_in[7];
    const float* bk    = (const float*)d_in[8];
    const float* Wv    = (const float*)d_in[9];
    const float* bv    = (const float*)d_in[10];
    const float* embW  = (const float*)d_in[11];
    const float* embB  = (const float*)d_in[12];
    const float* g2    = (const float*)d_in[13];
    const float* b2    = (const float*)d_in[14];
    const float* outW  = (const float*)d_in[15];
    const float* outB  = (const float*)d_in[16];
    float* out = (float*)d_out;

    static int smem_set = 0;
    if (!smem_set) {
        cudaFuncSetAttribute(gemm_k, cudaFuncAttributeMaxDynamicSharedMemorySize, SMEM_BYTES);
        smem_set = 1;
    }

    zero_k <<<512, 256>>>(embB);
    wconv_k<<<dim3(16, 16, 4), dim3(32, 8)>>>(Wq, Wk, Wv, outW);
    emb_k  <<<dim3(Bb, 8, 8), 256>>>(emb, embW);
    ln_k   <<<NTOK, 128>>>(x, gamma, beta);
    gemm_k <<<dim3(12, NTOK/256), 256, SMEM_BYTES>>>(0, bq, bk, bv, mask, nullptr, nullptr);
    kv_k   <<<dim3(Bb*Hh, 16), 128>>>();
    y_k    <<<dim3(Bb*Hh, Tt/64), 128>>>();
    style_k<<<NTOK, 128>>>(g2, b2);
    gemm_k <<<dim3(4, NTOK/256), 256, SMEM_BYTES>>>(1, outB, nullptr, nullptr, nullptr, x, out);
}

// round 6
// speedup vs baseline: 6.2881x; 1.0965x over previous
#include <cuda_runtime.h>
#include <cuda_fp16.h>
#include <math.h>
#include <stdint.h>

#define Bb   4
#define Tt   8192
#define Dd   512
#define Hh   8
#define DH   64
#define TEE  2048
#define NTOK (Bb*Tt)

// ---------------- scratch ----------------
__device__ __half g_xn[NTOK*Dd];           // LN(x), fp16
__device__ __half g_hs[NTOK*Dd];           // silu(stylized), fp16
__device__ __half g_qkvT[3*Dd*Dd];         // [1536][512] W^T fp16
__device__ __half g_outT[Dd*Dd];           // [512][512]  W^T fp16
__device__ float g_qs[NTOK*Dd];
__device__ float g_ek[NTOK*Dd];
__device__ float g_vv[NTOK*Dd];
__device__ float g_y [NTOK*Dd];
__device__ float g_ksum[Bb*Dd];
__device__ float g_attn[Bb*Hh*DH*DH];
__device__ float g_emb[Bb*2*Dd];

// ---------------- helpers ----------------
__device__ __forceinline__ uint32_t smem_u32(const void* p) {
    uint32_t a;
    asm("{ .reg .u64 t; cvta.to.shared.u64 t, %1; cvt.u32.u64 %0, t; }" : "=r"(a) : "l"(p));
    return a;
}
__device__ __forceinline__ void cp16(void* dst, const void* src) {
    uint32_t d;
    asm("{ .reg .u64 t; cvta.to.shared.u64 t, %1; cvt.u32.u64 %0, t; }" : "=r"(d) : "l"(dst));
    asm volatile("cp.async.cg.shared.global [%0], [%1], 16;" :: "r"(d), "l"(src) : "memory");
}
__device__ __forceinline__ void ldsm4(uint32_t* r, uint32_t addr) {
    asm volatile("ldmatrix.sync.aligned.m8n8.x4.shared.b16 {%0,%1,%2,%3}, [%4];"
        : "=r"(r[0]), "=r"(r[1]), "=r"(r[2]), "=r"(r[3]) : "r"(addr));
}
__device__ __forceinline__ void mma_f16(float* c, const uint32_t* a, const uint32_t* b) {
    asm volatile(
        "mma.sync.aligned.m16n8k16.row.col.f32.f16.f16.f32 "
        "{%0,%1,%2,%3}, {%4,%5,%6,%7}, {%8,%9}, {%0,%1,%2,%3};"
        : "+f"(c[0]), "+f"(c[1]), "+f"(c[2]), "+f"(c[3])
        : "r"(a[0]), "r"(a[1]), "r"(a[2]), "r"(a[3]), "r"(b[0]), "r"(b[1]));
}
__device__ __forceinline__ void mma_tf32(float* c, const uint32_t* a, const uint32_t* b) {
    asm volatile(
        "mma.sync.aligned.m16n8k8.row.col.f32.tf32.tf32.f32 "
        "{%0,%1,%2,%3}, {%4,%5,%6,%7}, {%8,%9}, {%0,%1,%2,%3};"
        : "+f"(c[0]), "+f"(c[1]), "+f"(c[2]), "+f"(c[3])
        : "r"(a[0]), "r"(a[1]), "r"(a[2]), "r"(a[3]), "r"(b[0]), "r"(b[1]));
}

// ---------------- zero accumulators + seed emb with bias ----------------
__global__ void zero_k(const float* __restrict__ embB) {
    int i = blockIdx.x * blockDim.x + threadIdx.x;
    if (i < Bb*Dd) g_ksum[i] = 0.f;
    if (i < Bb*Hh*DH*DH) g_attn[i] = 0.f;
    if (i < Bb*2*Dd) g_emb[i] = embB[i & (2*Dd - 1)];
}

// ---------------- weight transpose + fp16 ----------------
__global__ void wconv_k(const float* __restrict__ Wq, const float* __restrict__ Wk,
                        const float* __restrict__ Wv, const float* __restrict__ Wo) {
    __shared__ float t[32][33];
    int mat = blockIdx.z;
    const float* W = mat == 0 ? Wq : mat == 1 ? Wk : mat == 2 ? Wv : Wo;
    int k0 = blockIdx.y * 32, n0 = blockIdx.x * 32;
    int tx = threadIdx.x, ty = threadIdx.y;
    #pragma unroll
    for (int i = 0; i < 4; i++)
        t[ty + i*8][tx] = W[(size_t)(k0 + ty + i*8)*Dd + n0 + tx];
    __syncthreads();
    __half* dst = (mat < 3) ? g_qkvT : g_outT;
    int nbase = (mat < 3) ? mat*Dd : 0;
    #pragma unroll
    for (int i = 0; i < 4; i++) {
        int n = n0 + ty + i*8, k = k0 + tx;
        dst[(size_t)(nbase + n)*Dd + k] = __float2half_rn(t[tx][ty + i*8]);
    }
}

// ---------------- emb partial: silu(emb_chunk) @ W_chunk, atomic add ----------
__global__ void emb_k(const float* __restrict__ emb,
                      const float* __restrict__ W) {
    __shared__ float se[256];
    int b = blockIdx.x, oc = blockIdx.y, ec = blockIdx.z;
    int tid = threadIdx.x;
    if (tid < 128) {
        #pragma unroll
        for (int i = 0; i < 2; i++) {
            float e = emb[b*TEE + ec*256 + tid*2 + i];
            se[tid*2 + i] = e / (1.f + __expf(-e));
        }
    }
    __syncthreads();
    int o = oc*128 + (tid & 127);
    int eh = (tid >> 7) * 128;
    float acc = 0.f;
    #pragma unroll 4
    for (int e = 0; e < 128; e++)
        acc += se[eh + e] * W[(size_t)(ec*256 + eh + e)*(2*Dd) + o];
    atomicAdd(&g_emb[b*2*Dd + o], acc);
}

// ---------------- LN(x) -> g_xn (fp16) ----------------
__global__ void ln_k(const float* __restrict__ x,
                     const float* __restrict__ g,
                     const float* __restrict__ be) {
    int tok = blockIdx.x, tid = threadIdx.x;
    float4 v = ((const float4*)(x + (size_t)tok*Dd))[tid];
    float s = v.x + v.y + v.z + v.w;
    __shared__ float r1[4], r2[4];
    for (int o = 16; o; o >>= 1) s += __shfl_xor_sync(0xffffffffu, s, o);
    if ((tid & 31) == 0) r1[tid >> 5] = s;
    __syncthreads();
    float mu = (r1[0] + r1[1] + r1[2] + r1[3]) * (1.f / Dd);
    float a = v.x - mu, b = v.y - mu, c = v.z - mu, d = v.w - mu;
    float ss = a*a + b*b + c*c + d*d;
    for (int o = 16; o; o >>= 1) ss += __shfl_xor_sync(0xffffffffu, ss, o);
    if ((tid & 31) == 0) r2[tid >> 5] = ss;
    __syncthreads();
    float var = (r2[0] + r2[1] + r2[2] + r2[3]) * (1.f / Dd);
    float rs = rsqrtf(var + 1e-5f);
    float4 gg = ((const float4*)g)[tid], bb = ((const float4*)be)[tid];
    __half2* ph = (__half2*)(g_xn + (size_t)tok*Dd);
    ph[tid*2]   = __halves2half2(__float2half_rn(a*rs*gg.x + bb.x),
                                 __float2half_rn(b*rs*gg.y + bb.y));
    ph[tid*2+1] = __halves2half2(__float2half_rn(c*rs*gg.z + bb.z),
                                 __float2half_rn(d*rs*gg.w + bb.w));
}

// ---------------- fp16 HMMA GEMM: BM=256, BN=128, BK=64, ldmatrix, 3-stage ----
#define AROW 72                            // halves per smem row (64 + 8 pad)
#define STG_A (256*AROW)                   // halves
#define STG_B (128*AROW)
#define STAGE_H (STG_A + STG_B)            // 27648 halves = 55296 B
#define SMEM_BYTES (3*STAGE_H*2)           // 165888 B (> C staging 135168)

__device__ __forceinline__ void copy_stage(__half* smh, int st, int kc,
    const __half* __restrict__ Ag, const __half* __restrict__ Bg,
    int m0, int n0, int tid)
{
    __half* A = smh + st*STAGE_H;
    __half* B = A + STG_A;
    #pragma unroll
    for (int i = 0; i < 8; i++) {           // A: 256 rows x 8 chunks of 8 halves
        int s = tid + i*256;
        int r = s >> 3, c8 = s & 7;
        cp16(A + r*AROW + c8*8, Ag + (size_t)(m0 + r)*Dd + kc*64 + c8*8);
    }
    #pragma unroll
    for (int i = 0; i < 4; i++) {           // B: 128 rows x 8 chunks
        int s = tid + i*256;
        int r = s >> 3, c8 = s & 7;
        cp16(B + r*AROW + c8*8, Bg + (size_t)(n0 + r)*Dd + kc*64 + c8*8);
    }
    asm volatile("cp.async.commit_group;" ::: "memory");
}

__global__ __launch_bounds__(256, 1) void gemm_k(
    int mode,                       // 0 = QKV, 1 = OUT
    const float* __restrict__ b0, const float* __restrict__ b1, const float* __restrict__ b2,
    const float* __restrict__ mask, const float* __restrict__ xres, float* __restrict__ outp)
{
    extern __shared__ __half smh[];
    uint32_t smb = smem_u32(smh);
    int tid = threadIdx.x;
    int lane = tid & 31, w = tid >> 5;
    int g = lane >> 2, cq = lane & 3;
    int wm = w >> 1, wn = w & 1;           // 4 x 2 warps, 64x64 tiles
    int mBase = wm*64, nBase = wn*64;
    int m0 = blockIdx.y * 256;
    int n0 = blockIdx.x * 128;

    const __half* Ag = mode ? g_hs : g_xn;
    const __half* Bg = mode ? g_outT : g_qkvT;

    // ldmatrix lane->address mapping (byte offsets within stage)
    uint32_t aoff[4], boff[4];
    {
        int ar = lane & 15;                 // rows 0..15
        int ac = (lane >> 4) * 8;           // k-half select
        #pragma unroll
        for (int mt = 0; mt < 4; mt++)
            aoff[mt] = (uint32_t)(((mBase + mt*16 + ar)*AROW + ac) * 2);
        int br = ((lane >> 4) << 3) | (lane & 7);   // 0..7 then 8..15 (nt pair)
        int bc = ((lane >> 3) & 1) * 8;
        #pragma unroll
        for (int p = 0; p < 4; p++)
            boff[p] = (uint32_t)(((nBase + p*16 + br)*AROW + bc) * 2 + STG_A*2);
    }

    float acc[4][8][4];
    #pragma unroll
    for (int i = 0; i < 4; i++)
        #pragma unroll
        for (int j = 0; j < 8; j++)
            #pragma unroll
            for (int r = 0; r < 4; r++) acc[i][j][r] = 0.f;

    copy_stage(smh, 0, 0, Ag, Bg, m0, n0, tid);
    copy_stage(smh, 1, 1, Ag, Bg, m0, n0, tid);

    const int NIT = Dd/64;                 // 8
    for (int it = 0; it < NIT; it++) {
        if (it + 2 < NIT) copy_stage(smh, (it+2)%3, it+2, Ag, Bg, m0, n0, tid);
        if (it + 2 < NIT)      asm volatile("cp.async.wait_group 2;" ::: "memory");
        else if (it + 1 < NIT) asm volatile("cp.async.wait_group 1;" ::: "memory");
        else                   asm volatile("cp.async.wait_group 0;" ::: "memory");
        __syncthreads();

        uint32_t stageB = smb + (uint32_t)((it%3)*STAGE_H*2);
        #pragma unroll
        for (int k16 = 0; k16 < 4; k16++) {
            uint32_t kb = (uint32_t)(k16*32);
            uint32_t a[4][4], bb[4][4];
            #pragma unroll
            for (int mt = 0; mt < 4; mt++) ldsm4(a[mt], stageB + aoff[mt] + kb);
            #pragma unroll
            for (int p = 0; p < 4; p++)    ldsm4(bb[p], stageB + boff[p] + kb);
            #pragma unroll
            for (int mt = 0; mt < 4; mt++)
                #pragma unroll
                for (int p = 0; p < 4; p++) {
                    mma_f16(acc[mt][2*p],   a[mt], &bb[p][0]);
                    mma_f16(acc[mt][2*p+1], a[mt], &bb[p][2]);
                }
        }
        __syncthreads();
    }

    // stage C tile to shared (reuse pipeline smem)
    float (*Cs)[132] = (float (*)[132])smh;
    #pragma unroll
    for (int mt = 0; mt < 4; mt++) {
        int r = mBase + mt*16 + g;
        #pragma unroll
        for (int nt = 0; nt < 8; nt++) {
            int cc = nBase + nt*8 + cq*2;
            Cs[r][cc]     = acc[mt][nt][0];
            Cs[r][cc+1]   = acc[mt][nt][1];
            Cs[r+8][cc]   = acc[mt][nt][2];
            Cs[r+8][cc+1] = acc[mt][nt][3];
        }
    }
    __syncthreads();

    // epilogue: thread = one row (256 rows), loop over 64-col halves
    int row = tid;
    int m = m0 + row;
    int region = n0 >> 9;
    if (mode == 1) {
        #pragma unroll
        for (int half = 0; half < 2; half++) {
            int ngl = n0 + half*64;
            const float* crow = &Cs[row][half*64];
            #pragma unroll
            for (int j = 0; j < 64; j += 4) {
                size_t off = (size_t)m*Dd + ngl + j;
                float4 xr = *(const float4*)(xres + off);
                float4 o;
                o.x = crow[j]   + b0[ngl+j]   + xr.x;
                o.y = crow[j+1] + b0[ngl+j+1] + xr.y;
                o.z = crow[j+2] + b0[ngl+j+2] + xr.z;
                o.w = crow[j+3] + b0[ngl+j+3] + xr.w;
                *(float4*)(outp + off) = o;
            }
        }
    } else if (region == 0) {
        #pragma unroll
        for (int half = 0; half < 2; half++) {
            int c5 = (n0 & 511) + half*64;
            const float* crow = &Cs[row][half*64];
            float v[64];
            float mx = -1e30f;
            #pragma unroll
            for (int j = 0; j < 64; j++) { v[j] = crow[j] + b0[c5+j]; mx = fmaxf(mx, v[j]); }
            float s = 0.f;
            #pragma unroll
            for (int j = 0; j < 64; j++) { v[j] = __expf(v[j] - mx); s += v[j]; }
            float inv = 1.f / s;
            #pragma unroll
            for (int j = 0; j < 64; j += 4) {
                float4 o; o.x = v[j]*inv; o.y = v[j+1]*inv; o.z = v[j+2]*inv; o.w = v[j+3]*inv;
                *(float4*)(g_qs + (size_t)m*Dd + c5 + j) = o;
            }
        }
    } else if (region == 1) {
        float madd = (1.f - mask[m]) * (-1e6f);
        #pragma unroll
        for (int half = 0; half < 2; half++) {
            int c5 = (n0 & 511) + half*64;
            float* crow = &Cs[row][half*64];
            float v[64];
            #pragma unroll
            for (int j = 0; j < 64; j++) v[j] = __expf(crow[j] + b1[c5+j] + madd);
            #pragma unroll
            for (int j = 0; j < 64; j += 4) {
                float4 o; o.x = v[j]; o.y = v[j+1]; o.z = v[j+2]; o.w = v[j+3];
                *(float4*)(g_ek + (size_t)m*Dd + c5 + j) = o;
            }
            #pragma unroll
            for (int j = 0; j < 64; j++) crow[j] = v[j];   // for column sums
        }
        __syncthreads();
        if (tid < 128) {
            float s = 0.f;
            #pragma unroll 8
            for (int r = 0; r < 256; r++) s += Cs[r][tid];
            atomicAdd(&g_ksum[(m0 >> 13)*Dd + (n0 & 511) + tid], s);
        }
    } else {
        float mv = mask[m];
        #pragma unroll
        for (int half = 0; half < 2; half++) {
            int c5 = (n0 & 511) + half*64;
            const float* crow = &Cs[row][half*64];
            #pragma unroll
            for (int j = 0; j < 64; j += 4) {
                float4 o;
                o.x = (crow[j]   + b2[c5+j]  ) * mv;
                o.y = (crow[j+1] + b2[c5+j+1]) * mv;
                o.z = (crow[j+2] + b2[c5+j+2]) * mv;
                o.w = (crow[j+3] + b2[c5+j+3]) * mv;
                *(float4*)(g_vv + (size_t)m*Dd + c5 + j) = o;
            }
        }
    }
}

// ---------------- KV state (tf32 tensor) ----------------
__global__ __launch_bounds__(128) void kv_k() {
    __shared__ float Es[64][72];
    __shared__ float Vs[64][72];
    int bh = blockIdx.x; int b = bh >> 3; int h = bh & 7;
    int t0 = b*Tt + blockIdx.y * 512;
    int tid = threadIdx.x;
    int lane = tid & 31, w = tid >> 5;
    int g = lane >> 2, cq = lane & 3;
    int mBase = w * 16;

    float acc[8][4];
    #pragma unroll
    for (int i = 0; i < 8; i++)
        #pragma unroll
        for (int r = 0; r < 4; r++) acc[i][r] = 0.f;

    for (int tile = 0; tile < 8; tile++) {
        #pragma unroll
        for (int i = 0; i < 8; i++) {
            int s = tid + i*128;
            int r = s >> 4, c4 = s & 15;
            size_t base = (size_t)(t0 + tile*64 + r)*Dd + h*DH + c4*4;
            *(float4*)&Es[r][c4*4] = *(const float4*)(g_ek + base);
            *(float4*)&Vs[r][c4*4] = *(const float4*)(g_vv + base);
        }
        __syncthreads();
        #pragma unroll
        for (int k8 = 0; k8 < 8; k8++) {
            int kk = k8*8;
            uint32_t a[4], bfr[8][2];
            a[0] = __float_as_uint(Es[kk+cq][mBase+g]);
            a[1] = __float_as_uint(Es[kk+cq][mBase+g+8]);
            a[2] = __float_as_uint(Es[kk+cq+4][mBase+g]);
            a[3] = __float_as_uint(Es[kk+cq+4][mBase+g+8]);
            #pragma unroll
            for (int nt = 0; nt < 8; nt++) {
                bfr[nt][0] = __float_as_uint(Vs[kk+cq][nt*8+g]);
                bfr[nt][1] = __float_as_uint(Vs[kk+cq+4][nt*8+g]);
            }
            #pragma unroll
            for (int nt = 0; nt < 8; nt++)
                mma_tf32(acc[nt], a, bfr[nt]);
        }
        __syncthreads();
    }
    float* A = g_attn + (size_t)bh*DH*DH;
    #pragma unroll
    for (int nt = 0; nt < 8; nt++) {
        int n = nt*8 + cq*2;
        atomicAdd(&A[(mBase+g)*DH + n],     acc[nt][0]);
        atomicAdd(&A[(mBase+g)*DH + n+1],   acc[nt][1]);
        atomicAdd(&A[(mBase+g+8)*DH + n],   acc[nt][2]);
        atomicAdd(&A[(mBase+g+8)*DH + n+1], acc[nt][3]);
    }
}

// ---------------- y = q_h @ (attn_h / ksum) (tf32 tensor) ----------------
__global__ __launch_bounds__(128) void y_k() {
    __shared__ float Qs[64][68];
    __shared__ float Ahs[64][72];
    int bh = blockIdx.x; int b = bh >> 3; int h = bh & 7;
    int t0 = b*Tt + blockIdx.y * 64;
    int tid = threadIdx.x;
    int lane = tid & 31, w = tid >> 5;
    int g = lane >> 2, cq = lane & 3;
    int mBase = w * 16;

    {
        const float* A  = g_attn + (size_t)bh*DH*DH;
        const float* ks = g_ksum + b*Dd + h*DH;
        #pragma unroll
        for (int i = 0; i < 8; i++) {
            int s = tid + i*128;
            int r = s >> 4, c4 = s & 15;
            float rk = 1.f / ks[r];
            float4 a = *(const float4*)(A + r*DH + c4*4);
            a.x *= rk; a.y *= rk; a.z *= rk; a.w *= rk;
            *(float4*)&Ahs[r][c4*4] = a;
            *(float4*)&Qs[r][c4*4] = *(const float4*)(g_qs + (size_t)(t0 + r)*Dd + h*DH + c4*4);
        }
    }
    __syncthreads();

    float acc[8][4];
    #pragma unroll
    for (int i = 0; i < 8; i++)
        #pragma unroll
        for (int r = 0; r < 4; r++) acc[i][r] = 0.f;

    #pragma unroll
    for (int k8 = 0; k8 < 8; k8++) {
        int kk = k8*8;
        uint32_t a[4], bfr[8][2];
        a[0] = __float_as_uint(Qs[mBase+g][kk+cq]);
        a[1] = __float_as_uint(Qs[mBase+g+8][kk+cq]);
        a[2] = __float_as_uint(Qs[mBase+g][kk+cq+4]);
        a[3] = __float_as_uint(Qs[mBase+g+8][kk+cq+4]);
        #pragma unroll
        for (int nt = 0; nt < 8; nt++) {
            bfr[nt][0] = __float_as_uint(Ahs[kk+cq][nt*8+g]);
            bfr[nt][1] = __float_as_uint(Ahs[kk+cq+4][nt*8+g]);
        }
        #pragma unroll
        for (int nt = 0; nt < 8; nt++)
            mma_tf32(acc[nt], a, bfr[nt]);
    }

    #pragma unroll
    for (int nt = 0; nt < 8; nt++) {
        int n = h*DH + nt*8 + cq*2;
        size_t r0 = (size_t)(t0 + mBase + g)*Dd + n;
        size_t r1 = (size_t)(t0 + mBase + g + 8)*Dd + n;
        *(float2*)(g_y + r0) = make_float2(acc[nt][0], acc[nt][1]);
        *(float2*)(g_y + r1) = make_float2(acc[nt][2], acc[nt][3]);
    }
}

// ---------------- stylize + silu -> g_hs (fp16) ----------------
__global__ void style_k(const float* __restrict__ g2, const float* __restrict__ b2) {
    int tok = blockIdx.x, tid = threadIdx.x;
    int b = tok >> 13;
    float4 v = ((const float4*)(g_y + (size_t)tok*Dd))[tid];
    float s = v.x + v.y + v.z + v.w;
    __shared__ float r1[4], r2[4];
    for (int o = 16; o; o >>= 1) s += __shfl_xor_sync(0xffffffffu, s, o);
    if ((tid & 31) == 0) r1[tid >> 5] = s;
    __syncthreads();
    float mu = (r1[0] + r1[1] + r1[2] + r1[3]) * (1.f / Dd);
    float a = v.x - mu, bb_ = v.y - mu, c = v.z - mu, d = v.w - mu;
    float ss = a*a + bb_*bb_ + c*c + d*d;
    for (int o = 16; o; o >>= 1) ss += __shfl_xor_sync(0xffffffffu, ss, o);
    if ((tid & 31) == 0) r2[tid >> 5] = ss;
    __syncthreads();
    float var = (r2[0] + r2[1] + r2[2] + r2[3]) * (1.f / Dd);
    float rs = rsqrtf(var + 1e-5f);
    float4 gg = ((const float4*)g2)[tid], bt = ((const float4*)b2)[tid];
    float4 sc = ((const float4*)(g_emb + b*2*Dd))[tid];
    float4 sh = ((const float4*)(g_emb + b*2*Dd + Dd))[tid];
    float h0 = (a  *rs*gg.x + bt.x)*(1.f + sc.x) + sh.x;
    float h1 = (bb_*rs*gg.y + bt.y)*(1.f + sc.y) + sh.y;
    float h2 = (c  *rs*gg.z + bt.z)*(1.f + sc.z) + sh.z;
    float h3 = (d  *rs*gg.w + bt.w)*(1.f + sc.w) + sh.w;
    h0 = h0 / (1.f + __expf(-h0));
    h1 = h1 / (1.f + __expf(-h1));
    h2 = h2 / (1.f + __expf(-h2));
    h3 = h3 / (1.f + __expf(-h3));
    __half2* ph = (__half2*)(g_hs + (size_t)tok*Dd);
    ph[tid*2]   = __halves2half2(__float2half_rn(h0), __float2half_rn(h1));
    ph[tid*2+1] = __halves2half2(__float2half_rn(h2), __float2half_rn(h3));
}

// ---------------- launch ----------------
extern "C" void kernel_launch(void* const* d_in, const int* in_sizes, int n_in,
                              void* d_out, int out_size) {
    const float* x     = (const float*)d_in[0];
    const float* emb   = (const float*)d_in[1];
    const float* mask  = (const float*)d_in[2];
    const float* gamma = (const float*)d_in[3];
    const float* beta  = (const float*)d_in[4];
    const float* Wq    = (const float*)d_in[5];
    const float* bq    = (const float*)d_in[6];
    const float* Wk    = (const float*)d_in[7];
    const float* bk    = (const float*)d_in[8];
    const float* Wv    = (const float*)d_in[9];
    const float* bv    = (const float*)d_in[10];
    const float* embW  = (const float*)d_in[11];
    const float* embB  = (const float*)d_in[12];
    const float* g2    = (const float*)d_in[13];
    const float* b2    = (const float*)d_in[14];
    const float* outW  = (const float*)d_in[15];
    const float* outB  = (const float*)d_in[16];
    float* out = (float*)d_out;

    static int smem_set = 0;
    if (!smem_set) {
        cudaFuncSetAttribute(gemm_k, cudaFuncAttributeMaxDynamicSharedMemorySize, SMEM_BYTES);
        smem_set = 1;
    }

    zero_k <<<512, 256>>>(embB);
    wconv_k<<<dim3(16, 16, 4), dim3(32, 8)>>>(Wq, Wk, Wv, outW);
    emb_k  <<<dim3(Bb, 8, 8), 256>>>(emb, embW);
    ln_k   <<<NTOK, 128>>>(x, gamma, beta);
    gemm_k <<<dim3(12, NTOK/256), 256, SMEM_BYTES>>>(0, bq, bk, bv, mask, nullptr, nullptr);
    kv_k   <<<dim3(Bb*Hh, 16), 128>>>();
    y_k    <<<dim3(Bb*Hh, Tt/64), 128>>>();
    style_k<<<NTOK, 128>>>(g2, b2);
    gemm_k <<<dim3(4, NTOK/256), 256, SMEM_BYTES>>>(1, outB, nullptr, nullptr, nullptr, x, out);
}

// round 7
// speedup vs baseline: 7.9488x; 1.2641x over previous
#include <cuda_runtime.h>
#include <cuda_fp16.h>
#include <math.h>
#include <stdint.h>

#define Bb   4
#define Tt   8192
#define Dd   512
#define Hh   8
#define DH   64
#define TEE  2048
#define NTOK (Bb*Tt)

// ---------------- scratch ----------------
__device__ __half g_xn[NTOK*Dd];           // LN(x), fp16
__device__ __half g_hs[NTOK*Dd];           // silu(stylized), fp16
__device__ __half g_qkvT[3*Dd*Dd];         // [1536][512] W^T fp16
__device__ __half g_outT[Dd*Dd];           // [512][512]  W^T fp16
__device__ __half g_qs[NTOK*Dd];           // softmaxed q, fp16
__device__ __half g_ek[NTOK*Dd];           // exp(k), fp16
__device__ __half g_vv[NTOK*Dd];           // masked v, fp16
__device__ __half g_y [NTOK*Dd];           // attention out, fp16
__device__ float g_ksum[Bb*Dd];
__device__ float g_attn[Bb*Hh*DH*DH];
__device__ float g_emb[Bb*2*Dd];

// ---------------- helpers ----------------
__device__ __forceinline__ uint32_t smem_u32(const void* p) {
    uint32_t a;
    asm("{ .reg .u64 t; cvta.to.shared.u64 t, %1; cvt.u32.u64 %0, t; }" : "=r"(a) : "l"(p));
    return a;
}
__device__ __forceinline__ void cp16(void* dst, const void* src) {
    uint32_t d;
    asm("{ .reg .u64 t; cvta.to.shared.u64 t, %1; cvt.u32.u64 %0, t; }" : "=r"(d) : "l"(dst));
    asm volatile("cp.async.cg.shared.global [%0], [%1], 16;" :: "r"(d), "l"(src) : "memory");
}
__device__ __forceinline__ void ldsm4(uint32_t* r, uint32_t addr) {
    asm volatile("ldmatrix.sync.aligned.m8n8.x4.shared.b16 {%0,%1,%2,%3}, [%4];"
        : "=r"(r[0]), "=r"(r[1]), "=r"(r[2]), "=r"(r[3]) : "r"(addr));
}
__device__ __forceinline__ void mma_f16(float* c, const uint32_t* a, const uint32_t* b) {
    asm volatile(
        "mma.sync.aligned.m16n8k16.row.col.f32.f16.f16.f32 "
        "{%0,%1,%2,%3}, {%4,%5,%6,%7}, {%8,%9}, {%0,%1,%2,%3};"
        : "+f"(c[0]), "+f"(c[1]), "+f"(c[2]), "+f"(c[3])
        : "r"(a[0]), "r"(a[1]), "r"(a[2]), "r"(a[3]), "r"(b[0]), "r"(b[1]));
}
__device__ __forceinline__ void mma_tf32(float* c, const uint32_t* a, const uint32_t* b) {
    asm volatile(
        "mma.sync.aligned.m16n8k8.row.col.f32.tf32.tf32.f32 "
        "{%0,%1,%2,%3}, {%4,%5,%6,%7}, {%8,%9}, {%0,%1,%2,%3};"
        : "+f"(c[0]), "+f"(c[1]), "+f"(c[2]), "+f"(c[3])
        : "r"(a[0]), "r"(a[1]), "r"(a[2]), "r"(a[3]), "r"(b[0]), "r"(b[1]));
}

// ---------------- zero accumulators + seed emb with bias ----------------
__global__ void zero_k(const float* __restrict__ embB) {
    int i = blockIdx.x * blockDim.x + threadIdx.x;
    if (i < Bb*Dd) g_ksum[i] = 0.f;
    if (i < Bb*Hh*DH*DH) g_attn[i] = 0.f;
    if (i < Bb*2*Dd) g_emb[i] = embB[i & (2*Dd - 1)];
}

// ---------------- weight transpose + fp16 ----------------
__global__ void wconv_k(const float* __restrict__ Wq, const float* __restrict__ Wk,
                        const float* __restrict__ Wv, const float* __restrict__ Wo) {
    __shared__ float t[32][33];
    int mat = blockIdx.z;
    const float* W = mat == 0 ? Wq : mat == 1 ? Wk : mat == 2 ? Wv : Wo;
    int k0 = blockIdx.y * 32, n0 = blockIdx.x * 32;
    int tx = threadIdx.x, ty = threadIdx.y;
    #pragma unroll
    for (int i = 0; i < 4; i++)
        t[ty + i*8][tx] = W[(size_t)(k0 + ty + i*8)*Dd + n0 + tx];
    __syncthreads();
    __half* dst = (mat < 3) ? g_qkvT : g_outT;
    int nbase = (mat < 3) ? mat*Dd : 0;
    #pragma unroll
    for (int i = 0; i < 4; i++) {
        int n = n0 + ty + i*8, k = k0 + tx;
        dst[(size_t)(nbase + n)*Dd + k] = __float2half_rn(t[tx][ty + i*8]);
    }
}

// ---------------- emb partial: silu(emb_chunk) @ W_chunk, atomic add ----------
__global__ void emb_k(const float* __restrict__ emb,
                      const float* __restrict__ W) {
    __shared__ float se[256];
    int b = blockIdx.x, oc = blockIdx.y, ec = blockIdx.z;
    int tid = threadIdx.x;
    if (tid < 128) {
        #pragma unroll
        for (int i = 0; i < 2; i++) {
            float e = emb[b*TEE + ec*256 + tid*2 + i];
            se[tid*2 + i] = e / (1.f + __expf(-e));
        }
    }
    __syncthreads();
    int o = oc*128 + (tid & 127);
    int eh = (tid >> 7) * 128;
    float acc = 0.f;
    #pragma unroll 4
    for (int e = 0; e < 128; e++)
        acc += se[eh + e] * W[(size_t)(ec*256 + eh + e)*(2*Dd) + o];
    atomicAdd(&g_emb[b*2*Dd + o], acc);
}

// ---------------- LN(x) -> g_xn (fp16) ----------------
__global__ void ln_k(const float* __restrict__ x,
                     const float* __restrict__ g,
                     const float* __restrict__ be) {
    int tok = blockIdx.x, tid = threadIdx.x;
    float4 v = ((const float4*)(x + (size_t)tok*Dd))[tid];
    float s = v.x + v.y + v.z + v.w;
    __shared__ float r1[4], r2[4];
    for (int o = 16; o; o >>= 1) s += __shfl_xor_sync(0xffffffffu, s, o);
    if ((tid & 31) == 0) r1[tid >> 5] = s;
    __syncthreads();
    float mu = (r1[0] + r1[1] + r1[2] + r1[3]) * (1.f / Dd);
    float a = v.x - mu, b = v.y - mu, c = v.z - mu, d = v.w - mu;
    float ss = a*a + b*b + c*c + d*d;
    for (int o = 16; o; o >>= 1) ss += __shfl_xor_sync(0xffffffffu, ss, o);
    if ((tid & 31) == 0) r2[tid >> 5] = ss;
    __syncthreads();
    float var = (r2[0] + r2[1] + r2[2] + r2[3]) * (1.f / Dd);
    float rs = rsqrtf(var + 1e-5f);
    float4 gg = ((const float4*)g)[tid], bb = ((const float4*)be)[tid];
    __half2* ph = (__half2*)(g_xn + (size_t)tok*Dd);
    ph[tid*2]   = __halves2half2(__float2half_rn(a*rs*gg.x + bb.x),
                                 __float2half_rn(b*rs*gg.y + bb.y));
    ph[tid*2+1] = __halves2half2(__float2half_rn(c*rs*gg.z + bb.z),
                                 __float2half_rn(d*rs*gg.w + bb.w));
}

// ---------------- fp16 HMMA GEMM: BM=256, BN=128, BK=64, ldmatrix, 3-stage ----
// register epilogue (no C staging)
#define AROW 72
#define STG_A (256*AROW)
#define STG_B (128*AROW)
#define STAGE_H (STG_A + STG_B)
#define SMEM_BYTES (3*STAGE_H*2)

__device__ __forceinline__ void copy_stage(__half* smh, int st, int kc,
    const __half* __restrict__ Ag, const __half* __restrict__ Bg,
    int m0, int n0, int tid)
{
    __half* A = smh + st*STAGE_H;
    __half* B = A + STG_A;
    #pragma unroll
    for (int i = 0; i < 8; i++) {
        int s = tid + i*256;
        int r = s >> 3, c8 = s & 7;
        cp16(A + r*AROW + c8*8, Ag + (size_t)(m0 + r)*Dd + kc*64 + c8*8);
    }
    #pragma unroll
    for (int i = 0; i < 4; i++) {
        int s = tid + i*256;
        int r = s >> 3, c8 = s & 7;
        cp16(B + r*AROW + c8*8, Bg + (size_t)(n0 + r)*Dd + kc*64 + c8*8);
    }
    asm volatile("cp.async.commit_group;" ::: "memory");
}

__global__ __launch_bounds__(256, 1) void gemm_k(
    int mode,                       // 0 = QKV, 1 = OUT
    const float* __restrict__ b0, const float* __restrict__ b1, const float* __restrict__ b2,
    const float* __restrict__ mask, const float* __restrict__ xres, float* __restrict__ outp)
{
    extern __shared__ __half smh[];
    uint32_t smb = smem_u32(smh);
    int tid = threadIdx.x;
    int lane = tid & 31, w = tid >> 5;
    int g = lane >> 2, cq = lane & 3;
    int wm = w >> 1, wn = w & 1;           // 4 x 2 warps, 64x64 tiles
    int mBase = wm*64, nBase = wn*64;
    int m0 = blockIdx.y * 256;
    int n0 = blockIdx.x * 128;

    const __half* Ag = mode ? g_hs : g_xn;
    const __half* Bg = mode ? g_outT : g_qkvT;

    uint32_t aoff[4], boff[4];
    {
        int ar = lane & 15;
        int ac = (lane >> 4) * 8;
        #pragma unroll
        for (int mt = 0; mt < 4; mt++)
            aoff[mt] = (uint32_t)(((mBase + mt*16 + ar)*AROW + ac) * 2);
        int br = ((lane >> 4) << 3) | (lane & 7);
        int bc = ((lane >> 3) & 1) * 8;
        #pragma unroll
        for (int p = 0; p < 4; p++)
            boff[p] = (uint32_t)(((nBase + p*16 + br)*AROW + bc) * 2 + STG_A*2);
    }

    float acc[4][8][4];
    #pragma unroll
    for (int i = 0; i < 4; i++)
        #pragma unroll
        for (int j = 0; j < 8; j++)
            #pragma unroll
            for (int r = 0; r < 4; r++) acc[i][j][r] = 0.f;

    copy_stage(smh, 0, 0, Ag, Bg, m0, n0, tid);
    copy_stage(smh, 1, 1, Ag, Bg, m0, n0, tid);

    const int NIT = Dd/64;                 // 8
    for (int it = 0; it < NIT; it++) {
        if (it + 2 < NIT) copy_stage(smh, (it+2)%3, it+2, Ag, Bg, m0, n0, tid);
        if (it + 2 < NIT)      asm volatile("cp.async.wait_group 2;" ::: "memory");
        else if (it + 1 < NIT) asm volatile("cp.async.wait_group 1;" ::: "memory");
        else                   asm volatile("cp.async.wait_group 0;" ::: "memory");
        __syncthreads();

        uint32_t stageB = smb + (uint32_t)((it%3)*STAGE_H*2);
        #pragma unroll
        for (int k16 = 0; k16 < 4; k16++) {
            uint32_t kb = (uint32_t)(k16*32);
            uint32_t a[4][4], bb[4][4];
            #pragma unroll
            for (int mt = 0; mt < 4; mt++) ldsm4(a[mt], stageB + aoff[mt] + kb);
            #pragma unroll
            for (int p = 0; p < 4; p++)    ldsm4(bb[p], stageB + boff[p] + kb);
            #pragma unroll
            for (int mt = 0; mt < 4; mt++)
                #pragma unroll
                for (int p = 0; p < 4; p++) {
                    mma_f16(acc[mt][2*p],   a[mt], &bb[p][0]);
                    mma_f16(acc[mt][2*p+1], a[mt], &bb[p][2]);
                }
        }
        __syncthreads();
    }

    // ---------------- register epilogue ----------------
    int region = n0 >> 9;
    const float* bia = (mode == 1) ? b0 : (region == 0 ? b0 : (region == 1 ? b1 : b2));
    int cbase = ((mode == 1) ? n0 : (n0 & 511)) + nBase + cq*2;
    float blo[8], bhi[8];
    #pragma unroll
    for (int nt = 0; nt < 8; nt++) { blo[nt] = bia[cbase + nt*8]; bhi[nt] = bia[cbase + nt*8 + 1]; }

    if (mode == 1) {
        #pragma unroll
        for (int mt = 0; mt < 4; mt++)
            #pragma unroll
            for (int rh = 0; rh < 2; rh++) {
                int m = m0 + mBase + mt*16 + g + rh*8;
                #pragma unroll
                for (int nt = 0; nt < 8; nt++) {
                    size_t off = (size_t)m*Dd + n0 + nBase + nt*8 + cq*2;
                    float2 xr = *(const float2*)(xres + off);
                    float2 o = make_float2(acc[mt][nt][2*rh]   + blo[nt] + xr.x,
                                           acc[mt][nt][2*rh+1] + bhi[nt] + xr.y);
                    *(float2*)(outp + off) = o;
                }
            }
    } else if (region == 0) {
        // q softmax: warp's 64-col span == one head; quad reduce
        #pragma unroll
        for (int mt = 0; mt < 4; mt++)
            #pragma unroll
            for (int rh = 0; rh < 2; rh++) {
                int m = m0 + mBase + mt*16 + g + rh*8;
                float v0[8], v1[8];
                float mx = -1e30f;
                #pragma unroll
                for (int nt = 0; nt < 8; nt++) {
                    v0[nt] = acc[mt][nt][2*rh]   + blo[nt];
                    v1[nt] = acc[mt][nt][2*rh+1] + bhi[nt];
                    mx = fmaxf(mx, fmaxf(v0[nt], v1[nt]));
                }
                mx = fmaxf(mx, __shfl_xor_sync(0xffffffffu, mx, 1));
                mx = fmaxf(mx, __shfl_xor_sync(0xffffffffu, mx, 2));
                float s = 0.f;
                #pragma unroll
                for (int nt = 0; nt < 8; nt++) {
                    v0[nt] = __expf(v0[nt] - mx); v1[nt] = __expf(v1[nt] - mx);
                    s += v0[nt] + v1[nt];
                }
                s += __shfl_xor_sync(0xffffffffu, s, 1);
                s += __shfl_xor_sync(0xffffffffu, s, 2);
                float inv = 1.f / s;
                #pragma unroll
                for (int nt = 0; nt < 8; nt++)
                    *(__half2*)(g_qs + (size_t)m*Dd + cbase + nt*8) =
                        __floats2half2_rn(v0[nt]*inv, v1[nt]*inv);
            }
    } else if (region == 1) {
        float cs0[8] = {}, cs1[8] = {};
        #pragma unroll
        for (int mt = 0; mt < 4; mt++)
            #pragma unroll
            for (int rh = 0; rh < 2; rh++) {
                int m = m0 + mBase + mt*16 + g + rh*8;
                float madd = (1.f - mask[m]) * (-1e6f);
                #pragma unroll
                for (int nt = 0; nt < 8; nt++) {
                    float e0 = __expf(acc[mt][nt][2*rh]   + blo[nt] + madd);
                    float e1 = __expf(acc[mt][nt][2*rh+1] + bhi[nt] + madd);
                    __half2 h2 = __floats2half2_rn(e0, e1);
                    *(__half2*)(g_ek + (size_t)m*Dd + cbase + nt*8) = h2;
                    float2 hf = __half22float2(h2);
                    cs0[nt] += hf.x; cs1[nt] += hf.y;
                }
            }
        #pragma unroll
        for (int o = 4; o <= 16; o <<= 1)
            #pragma unroll
            for (int nt = 0; nt < 8; nt++) {
                cs0[nt] += __shfl_xor_sync(0xffffffffu, cs0[nt], o);
                cs1[nt] += __shfl_xor_sync(0xffffffffu, cs1[nt], o);
            }
        if (lane < 4) {
            int batch = m0 >> 13;
            #pragma unroll
            for (int nt = 0; nt < 8; nt++) {
                atomicAdd(&g_ksum[batch*Dd + cbase + nt*8],     cs0[nt]);
                atomicAdd(&g_ksum[batch*Dd + cbase + nt*8 + 1], cs1[nt]);
            }
        }
    } else {
        #pragma unroll
        for (int mt = 0; mt < 4; mt++)
            #pragma unroll
            for (int rh = 0; rh < 2; rh++) {
                int m = m0 + mBase + mt*16 + g + rh*8;
                float mv = mask[m];
                #pragma unroll
                for (int nt = 0; nt < 8; nt++)
                    *(__half2*)(g_vv + (size_t)m*Dd + cbase + nt*8) =
                        __floats2half2_rn((acc[mt][nt][2*rh]   + blo[nt])*mv,
                                          (acc[mt][nt][2*rh+1] + bhi[nt])*mv);
            }
    }
}

// ---------------- KV state (tf32 tensor, fp16 inputs) ----------------
__global__ __launch_bounds__(128) void kv_k() {
    __shared__ float Es[64][72];
    __shared__ float Vs[64][72];
    int bh = blockIdx.x; int b = bh >> 3; int h = bh & 7;
    int t0 = b*Tt + blockIdx.y * 512;
    int tid = threadIdx.x;
    int lane = tid & 31, w = tid >> 5;
    int g = lane >> 2, cq = lane & 3;
    int mBase = w * 16;

    float acc[8][4];
    #pragma unroll
    for (int i = 0; i < 8; i++)
        #pragma unroll
        for (int r = 0; r < 4; r++) acc[i][r] = 0.f;

    for (int tile = 0; tile < 8; tile++) {
        #pragma unroll
        for (int i = 0; i < 8; i++) {
            int s = tid + i*128;
            int r = s >> 4, c4 = s & 15;
            size_t base = (size_t)(t0 + tile*64 + r)*Dd + h*DH + c4*4;
            const __half2* pe = (const __half2*)(g_ek + base);
            const __half2* pv = (const __half2*)(g_vv + base);
            float2 e0 = __half22float2(pe[0]), e1 = __half22float2(pe[1]);
            float2 v0 = __half22float2(pv[0]), v1 = __half22float2(pv[1]);
            *(float4*)&Es[r][c4*4] = make_float4(e0.x, e0.y, e1.x, e1.y);
            *(float4*)&Vs[r][c4*4] = make_float4(v0.x, v0.y, v1.x, v1.y);
        }
        __syncthreads();
        #pragma unroll
        for (int k8 = 0; k8 < 8; k8++) {
            int kk = k8*8;
            uint32_t a[4], bfr[8][2];
            a[0] = __float_as_uint(Es[kk+cq][mBase+g]);
            a[1] = __float_as_uint(Es[kk+cq][mBase+g+8]);
            a[2] = __float_as_uint(Es[kk+cq+4][mBase+g]);
            a[3] = __float_as_uint(Es[kk+cq+4][mBase+g+8]);
            #pragma unroll
            for (int nt = 0; nt < 8; nt++) {
                bfr[nt][0] = __float_as_uint(Vs[kk+cq][nt*8+g]);
                bfr[nt][1] = __float_as_uint(Vs[kk+cq+4][nt*8+g]);
            }
            #pragma unroll
            for (int nt = 0; nt < 8; nt++)
                mma_tf32(acc[nt], a, bfr[nt]);
        }
        __syncthreads();
    }
    float* A = g_attn + (size_t)bh*DH*DH;
    #pragma unroll
    for (int nt = 0; nt < 8; nt++) {
        int n = nt*8 + cq*2;
        atomicAdd(&A[(mBase+g)*DH + n],     acc[nt][0]);
        atomicAdd(&A[(mBase+g)*DH + n+1],   acc[nt][1]);
        atomicAdd(&A[(mBase+g+8)*DH + n],   acc[nt][2]);
        atomicAdd(&A[(mBase+g+8)*DH + n+1], acc[nt][3]);
    }
}

// ---------------- y = q_h @ (attn_h / ksum) (tf32 tensor, fp16 in/out) --------
__global__ __launch_bounds__(128) void y_k() {
    __shared__ float Qs[64][68];
    __shared__ float Ahs[64][72];
    int bh = blockIdx.x; int b = bh >> 3; int h = bh & 7;
    int t0 = b*Tt + blockIdx.y * 64;
    int tid = threadIdx.x;
    int lane = tid & 31, w = tid >> 5;
    int g = lane >> 2, cq = lane & 3;
    int mBase = w * 16;

    {
        const float* A  = g_attn + (size_t)bh*DH*DH;
        const float* ks = g_ksum + b*Dd + h*DH;
        #pragma unroll
        for (int i = 0; i < 8; i++) {
            int s = tid + i*128;
            int r = s >> 4, c4 = s & 15;
            float rk = 1.f / ks[r];
            float4 a = *(const float4*)(A + r*DH + c4*4);
            a.x *= rk; a.y *= rk; a.z *= rk; a.w *= rk;
            *(float4*)&Ahs[r][c4*4] = a;
            const __half2* pq = (const __half2*)(g_qs + (size_t)(t0 + r)*Dd + h*DH + c4*4);
            float2 q0 = __half22float2(pq[0]), q1 = __half22float2(pq[1]);
            *(float4*)&Qs[r][c4*4] = make_float4(q0.x, q0.y, q1.x, q1.y);
        }
    }
    __syncthreads();

    float acc[8][4];
    #pragma unroll
    for (int i = 0; i < 8; i++)
        #pragma unroll
        for (int r = 0; r < 4; r++) acc[i][r] = 0.f;

    #pragma unroll
    for (int k8 = 0; k8 < 8; k8++) {
        int kk = k8*8;
        uint32_t a[4], bfr[8][2];
        a[0] = __float_as_uint(Qs[mBase+g][kk+cq]);
        a[1] = __float_as_uint(Qs[mBase+g+8][kk+cq]);
        a[2] = __float_as_uint(Qs[mBase+g][kk+cq+4]);
        a[3] = __float_as_uint(Qs[mBase+g+8][kk+cq+4]);
        #pragma unroll
        for (int nt = 0; nt < 8; nt++) {
            bfr[nt][0] = __float_as_uint(Ahs[kk+cq][nt*8+g]);
            bfr[nt][1] = __float_as_uint(Ahs[kk+cq+4][nt*8+g]);
        }
        #pragma unroll
        for (int nt = 0; nt < 8; nt++)
            mma_tf32(acc[nt], a, bfr[nt]);
    }

    #pragma unroll
    for (int nt = 0; nt < 8; nt++) {
        int n = h*DH + nt*8 + cq*2;
        size_t r0 = (size_t)(t0 + mBase + g)*Dd + n;
        size_t r1 = (size_t)(t0 + mBase + g + 8)*Dd + n;
        *(__half2*)(g_y + r0) = __floats2half2_rn(acc[nt][0], acc[nt][1]);
        *(__half2*)(g_y + r1) = __floats2half2_rn(acc[nt][2], acc[nt][3]);
    }
}

// ---------------- stylize + silu -> g_hs (fp16 in/out) ----------------
__global__ void style_k(const float* __restrict__ g2, const float* __restrict__ b2) {
    int tok = blockIdx.x, tid = threadIdx.x;
    int b = tok >> 13;
    const __half2* py = (const __half2*)(g_y + (size_t)tok*Dd);
    float2 y01 = __half22float2(py[tid*2]);
    float2 y23 = __half22float2(py[tid*2+1]);
    float s = y01.x + y01.y + y23.x + y23.y;
    __shared__ float r1[4], r2[4];
    for (int o = 16; o; o >>= 1) s += __shfl_xor_sync(0xffffffffu, s, o);
    if ((tid & 31) == 0) r1[tid >> 5] = s;
    __syncthreads();
    float mu = (r1[0] + r1[1] + r1[2] + r1[3]) * (1.f / Dd);
    float a = y01.x - mu, bb_ = y01.y - mu, c = y23.x - mu, d = y23.y - mu;
    float ss = a*a + bb_*bb_ + c*c + d*d;
    for (int o = 16; o; o >>= 1) ss += __shfl_xor_sync(0xffffffffu, ss, o);
    if ((tid & 31) == 0) r2[tid >> 5] = ss;
    __syncthreads();
    float var = (r2[0] + r2[1] + r2[2] + r2[3]) * (1.f / Dd);
    float rs = rsqrtf(var + 1e-5f);
    float4 gg = ((const float4*)g2)[tid], bt = ((const float4*)b2)[tid];
    float4 sc = ((const float4*)(g_emb + b*2*Dd))[tid];
    float4 sh = ((const float4*)(g_emb + b*2*Dd + Dd))[tid];
    float h0 = (a  *rs*gg.x + bt.x)*(1.f + sc.x) + sh.x;
    float h1 = (bb_*rs*gg.y + bt.y)*(1.f + sc.y) + sh.y;
    float h2 = (c  *rs*gg.z + bt.z)*(1.f + sc.z) + sh.z;
    float h3 = (d  *rs*gg.w + bt.w)*(1.f + sc.w) + sh.w;
    h0 = h0 / (1.f + __expf(-h0));
    h1 = h1 / (1.f + __expf(-h1));
    h2 = h2 / (1.f + __expf(-h2));
    h3 = h3 / (1.f + __expf(-h3));
    __half2* ph = (__half2*)(g_hs + (size_t)tok*Dd);
    ph[tid*2]   = __halves2half2(__float2half_rn(h0), __float2half_rn(h1));
    ph[tid*2+1] = __halves2half2(__float2half_rn(h2), __float2half_rn(h3));
}

// ---------------- launch ----------------
extern "C" void kernel_launch(void* const* d_in, const int* in_sizes, int n_in,
                              void* d_out, int out_size) {
    const float* x     = (const float*)d_in[0];
    const float* emb   = (const float*)d_in[1];
    const float* mask  = (const float*)d_in[2];
    const float* gamma = (const float*)d_in[3];
    const float* beta  = (const float*)d_in[4];
    const float* Wq    = (const float*)d_in[5];
    const float* bq    = (const float*)d_in[6];
    const float* Wk    = (const float*)d_in[7];
    const float* bk    = (const float*)d_in[8];
    const float* Wv    = (const float*)d_in[9];
    const float* bv    = (const float*)d_in[10];
    const float* embW  = (const float*)d_in[11];
    const float* embB  = (const float*)d_in[12];
    const float* g2    = (const float*)d_in[13];
    const float* b2    = (const float*)d_in[14];
    const float* outW  = (const float*)d_in[15];
    const float* outB  = (const float*)d_in[16];
    float* out = (float*)d_out;

    static int smem_set = 0;
    if (!smem_set) {
        cudaFuncSetAttribute(gemm_k, cudaFuncAttributeMaxDynamicSharedMemorySize, SMEM_BYTES);
        smem_set = 1;
    }

    zero_k <<<512, 256>>>(embB);
    wconv_k<<<dim3(16, 16, 4), dim3(32, 8)>>>(Wq, Wk, Wv, outW);
    emb_k  <<<dim3(Bb, 8, 8), 256>>>(emb, embW);
    ln_k   <<<NTOK, 128>>>(x, gamma, beta);
    gemm_k <<<dim3(12, NTOK/256), 256, SMEM_BYTES>>>(0, bq, bk, bv, mask, nullptr, nullptr);
    kv_k   <<<dim3(Bb*Hh, 16), 128>>>();
    y_k    <<<dim3(Bb*Hh, Tt/64), 128>>>();
    style_k<<<NTOK, 128>>>(g2, b2);
    gemm_k <<<dim3(4, NTOK/256), 256, SMEM_BYTES>>>(1, outB, nullptr, nullptr, nullptr, x, out);
}

// round 8
// speedup vs baseline: 8.6976x; 1.0942x over previous
#include <cuda_runtime.h>
#include <cuda_fp16.h>
#include <math.h>
#include <stdint.h>

#define Bb   4
#define Tt   8192
#define Dd   512
#define Hh   8
#define DH   64
#define TEE  2048
#define NTOK (Bb*Tt)

// ---------------- scratch ----------------
__device__ __half g_xn[NTOK*Dd];           // LN(x), fp16
__device__ __half g_hs[NTOK*Dd];           // silu(stylized), fp16
__device__ __half g_qkvT[3*Dd*Dd];         // [1536][512] W^T fp16
__device__ __half g_outT[Dd*Dd];           // [512][512]  W^T fp16
__device__ __half g_qs[NTOK*Dd];           // softmaxed q, fp16
__device__ __half g_ek[NTOK*Dd];           // exp(k), fp16
__device__ __half g_vv[NTOK*Dd];           // masked v, fp16
__device__ __half g_y [NTOK*Dd];           // attention out, fp16
__device__ float g_ksum[Bb*Dd];
__device__ float g_attn[Bb*Hh*DH*DH];
__device__ float g_emb[Bb*2*Dd];

// ---------------- helpers ----------------
__device__ __forceinline__ uint32_t smem_u32(const void* p) {
    uint32_t a;
    asm("{ .reg .u64 t; cvta.to.shared.u64 t, %1; cvt.u32.u64 %0, t; }" : "=r"(a) : "l"(p));
    return a;
}
__device__ __forceinline__ void cp16(void* dst, const void* src) {
    uint32_t d;
    asm("{ .reg .u64 t; cvta.to.shared.u64 t, %1; cvt.u32.u64 %0, t; }" : "=r"(d) : "l"(dst));
    asm volatile("cp.async.cg.shared.global [%0], [%1], 16;" :: "r"(d), "l"(src) : "memory");
}
__device__ __forceinline__ void ldsm4(uint32_t* r, uint32_t addr) {
    asm volatile("ldmatrix.sync.aligned.m8n8.x4.shared.b16 {%0,%1,%2,%3}, [%4];"
        : "=r"(r[0]), "=r"(r[1]), "=r"(r[2]), "=r"(r[3]) : "r"(addr));
}
__device__ __forceinline__ void mma_f16(float* c, const uint32_t* a, const uint32_t* b) {
    asm volatile(
        "mma.sync.aligned.m16n8k16.row.col.f32.f16.f16.f32 "
        "{%0,%1,%2,%3}, {%4,%5,%6,%7}, {%8,%9}, {%0,%1,%2,%3};"
        : "+f"(c[0]), "+f"(c[1]), "+f"(c[2]), "+f"(c[3])
        : "r"(a[0]), "r"(a[1]), "r"(a[2]), "r"(a[3]), "r"(b[0]), "r"(b[1]));
}
__device__ __forceinline__ void mma_tf32(float* c, const uint32_t* a, const uint32_t* b) {
    asm volatile(
        "mma.sync.aligned.m16n8k8.row.col.f32.tf32.tf32.f32 "
        "{%0,%1,%2,%3}, {%4,%5,%6,%7}, {%8,%9}, {%0,%1,%2,%3};"
        : "+f"(c[0]), "+f"(c[1]), "+f"(c[2]), "+f"(c[3])
        : "r"(a[0]), "r"(a[1]), "r"(a[2]), "r"(a[3]), "r"(b[0]), "r"(b[1]));
}

// ---------------- zero accumulators + seed emb with bias ----------------
__global__ void zero_k(const float* __restrict__ embB) {
    int i = blockIdx.x * blockDim.x + threadIdx.x;
    if (i < Bb*Dd) g_ksum[i] = 0.f;
    if (i < Bb*Hh*DH*DH) g_attn[i] = 0.f;
    if (i < Bb*2*Dd) g_emb[i] = embB[i & (2*Dd - 1)];
}

// ---------------- weight transpose + fp16 ----------------
__global__ void wconv_k(const float* __restrict__ Wq, const float* __restrict__ Wk,
                        const float* __restrict__ Wv, const float* __restrict__ Wo) {
    __shared__ float t[32][33];
    int mat = blockIdx.z;
    const float* W = mat == 0 ? Wq : mat == 1 ? Wk : mat == 2 ? Wv : Wo;
    int k0 = blockIdx.y * 32, n0 = blockIdx.x * 32;
    int tx = threadIdx.x, ty = threadIdx.y;
    #pragma unroll
    for (int i = 0; i < 4; i++)
        t[ty + i*8][tx] = W[(size_t)(k0 + ty + i*8)*Dd + n0 + tx];
    __syncthreads();
    __half* dst = (mat < 3) ? g_qkvT : g_outT;
    int nbase = (mat < 3) ? mat*Dd : 0;
    #pragma unroll
    for (int i = 0; i < 4; i++) {
        int n = n0 + ty + i*8, k = k0 + tx;
        dst[(size_t)(nbase + n)*Dd + k] = __float2half_rn(t[tx][ty + i*8]);
    }
}

// ---------------- emb partial: silu(emb_chunk) @ W_chunk, atomic add ----------
__global__ void emb_k(const float* __restrict__ emb,
                      const float* __restrict__ W) {
    __shared__ float se[256];
    int b = blockIdx.x, oc = blockIdx.y, ec = blockIdx.z;
    int tid = threadIdx.x;
    if (tid < 128) {
        #pragma unroll
        for (int i = 0; i < 2; i++) {
            float e = emb[b*TEE + ec*256 + tid*2 + i];
            se[tid*2 + i] = e / (1.f + __expf(-e));
        }
    }
    __syncthreads();
    int o = oc*128 + (tid & 127);
    int eh = (tid >> 7) * 128;
    float acc = 0.f;
    #pragma unroll 4
    for (int e = 0; e < 128; e++)
        acc += se[eh + e] * W[(size_t)(ec*256 + eh + e)*(2*Dd) + o];
    atomicAdd(&g_emb[b*2*Dd + o], acc);
}

// ---------------- LN(x) -> g_xn (fp16) ----------------
__global__ void ln_k(const float* __restrict__ x,
                     const float* __restrict__ g,
                     const float* __restrict__ be) {
    int tok = blockIdx.x, tid = threadIdx.x;
    float4 v = ((const float4*)(x + (size_t)tok*Dd))[tid];
    float s = v.x + v.y + v.z + v.w;
    __shared__ float r1[4], r2[4];
    for (int o = 16; o; o >>= 1) s += __shfl_xor_sync(0xffffffffu, s, o);
    if ((tid & 31) == 0) r1[tid >> 5] = s;
    __syncthreads();
    float mu = (r1[0] + r1[1] + r1[2] + r1[3]) * (1.f / Dd);
    float a = v.x - mu, b = v.y - mu, c = v.z - mu, d = v.w - mu;
    float ss = a*a + b*b + c*c + d*d;
    for (int o = 16; o; o >>= 1) ss += __shfl_xor_sync(0xffffffffu, ss, o);
    if ((tid & 31) == 0) r2[tid >> 5] = ss;
    __syncthreads();
    float var = (r2[0] + r2[1] + r2[2] + r2[3]) * (1.f / Dd);
    float rs = rsqrtf(var + 1e-5f);
    float4 gg = ((const float4*)g)[tid], bb = ((const float4*)be)[tid];
    __half2* ph = (__half2*)(g_xn + (size_t)tok*Dd);
    ph[tid*2]   = __halves2half2(__float2half_rn(a*rs*gg.x + bb.x),
                                 __float2half_rn(b*rs*gg.y + bb.y));
    ph[tid*2+1] = __halves2half2(__float2half_rn(c*rs*gg.z + bb.z),
                                 __float2half_rn(d*rs*gg.w + bb.w));
}

// ---------------- fp16 HMMA GEMM: BM=128, BN=128, BK=64, 2 CTAs/SM ----------
#define AROW 72
#define STG_A (128*AROW)
#define STG_B (128*AROW)
#define STAGE_H (STG_A + STG_B)            // 18432 halves = 36864 B
#define SMEM_BYTES (3*STAGE_H*2)           // 110592 B -> 2 CTAs/SM

__device__ __forceinline__ void copy_stage(__half* smh, int st, int kc,
    const __half* __restrict__ Ag, const __half* __restrict__ Bg,
    int m0, int n0, int tid)
{
    __half* A = smh + st*STAGE_H;
    __half* B = A + STG_A;
    #pragma unroll
    for (int i = 0; i < 4; i++) {           // A: 128 rows x 8 chunks of 8 halves
        int s = tid + i*256;
        int r = s >> 3, c8 = s & 7;
        cp16(A + r*AROW + c8*8, Ag + (size_t)(m0 + r)*Dd + kc*64 + c8*8);
    }
    #pragma unroll
    for (int i = 0; i < 4; i++) {           // B: 128 rows x 8 chunks
        int s = tid + i*256;
        int r = s >> 3, c8 = s & 7;
        cp16(B + r*AROW + c8*8, Bg + (size_t)(n0 + r)*Dd + kc*64 + c8*8);
    }
    asm volatile("cp.async.commit_group;" ::: "memory");
}

__global__ __launch_bounds__(256, 2) void gemm_k(
    int mode,                       // 0 = QKV, 1 = OUT
    const float* __restrict__ b0, const float* __restrict__ b1, const float* __restrict__ b2,
    const float* __restrict__ mask, const float* __restrict__ xres, float* __restrict__ outp)
{
    extern __shared__ __half smh[];
    uint32_t smb = smem_u32(smh);
    int tid = threadIdx.x;
    int lane = tid & 31, w = tid >> 5;
    int g = lane >> 2, cq = lane & 3;
    int wm = w >> 1, wn = w & 1;           // 4 x 2 warps, 32x64 tiles
    int mBase = wm*32, nBase = wn*64;
    int m0 = blockIdx.y * 128;
    int n0 = blockIdx.x * 128;

    const __half* Ag = mode ? g_hs : g_xn;
    const __half* Bg = mode ? g_outT : g_qkvT;

    uint32_t aoff[2], boff[4];
    {
        int ar = lane & 15;
        int ac = (lane >> 4) * 8;
        #pragma unroll
        for (int mt = 0; mt < 2; mt++)
            aoff[mt] = (uint32_t)(((mBase + mt*16 + ar)*AROW + ac) * 2);
        int br = ((lane >> 4) << 3) | (lane & 7);
        int bc = ((lane >> 3) & 1) * 8;
        #pragma unroll
        for (int p = 0; p < 4; p++)
            boff[p] = (uint32_t)(((nBase + p*16 + br)*AROW + bc) * 2 + STG_A*2);
    }

    float acc[2][8][4];
    #pragma unroll
    for (int i = 0; i < 2; i++)
        #pragma unroll
        for (int j = 0; j < 8; j++)
            #pragma unroll
            for (int r = 0; r < 4; r++) acc[i][j][r] = 0.f;

    copy_stage(smh, 0, 0, Ag, Bg, m0, n0, tid);
    copy_stage(smh, 1, 1, Ag, Bg, m0, n0, tid);

    const int NIT = Dd/64;                 // 8
    for (int it = 0; it < NIT; it++) {
        if (it + 2 < NIT) copy_stage(smh, (it+2)%3, it+2, Ag, Bg, m0, n0, tid);
        if (it + 2 < NIT)      asm volatile("cp.async.wait_group 2;" ::: "memory");
        else if (it + 1 < NIT) asm volatile("cp.async.wait_group 1;" ::: "memory");
        else                   asm volatile("cp.async.wait_group 0;" ::: "memory");
        __syncthreads();

        uint32_t stageB = smb + (uint32_t)((it%3)*STAGE_H*2);
        #pragma unroll
        for (int k16 = 0; k16 < 4; k16++) {
            uint32_t kb = (uint32_t)(k16*32);
            uint32_t a[2][4], bb[4][4];
            #pragma unroll
            for (int mt = 0; mt < 2; mt++) ldsm4(a[mt], stageB + aoff[mt] + kb);
            #pragma unroll
            for (int p = 0; p < 4; p++)    ldsm4(bb[p], stageB + boff[p] + kb);
            #pragma unroll
            for (int mt = 0; mt < 2; mt++)
                #pragma unroll
                for (int p = 0; p < 4; p++) {
                    mma_f16(acc[mt][2*p],   a[mt], &bb[p][0]);
                    mma_f16(acc[mt][2*p+1], a[mt], &bb[p][2]);
                }
        }
        __syncthreads();
    }

    // ---------------- register epilogue ----------------
    int region = n0 >> 9;
    const float* bia = (mode == 1) ? b0 : (region == 0 ? b0 : (region == 1 ? b1 : b2));
    int cbase = ((mode == 1) ? n0 : (n0 & 511)) + nBase + cq*2;
    float blo[8], bhi[8];
    #pragma unroll
    for (int nt = 0; nt < 8; nt++) { blo[nt] = bia[cbase + nt*8]; bhi[nt] = bia[cbase + nt*8 + 1]; }

    if (mode == 1) {
        #pragma unroll
        for (int mt = 0; mt < 2; mt++)
            #pragma unroll
            for (int rh = 0; rh < 2; rh++) {
                int m = m0 + mBase + mt*16 + g + rh*8;
                #pragma unroll
                for (int nt = 0; nt < 8; nt++) {
                    size_t off = (size_t)m*Dd + n0 + nBase + nt*8 + cq*2;
                    float2 xr = *(const float2*)(xres + off);
                    float2 o = make_float2(acc[mt][nt][2*rh]   + blo[nt] + xr.x,
                                           acc[mt][nt][2*rh+1] + bhi[nt] + xr.y);
                    *(float2*)(outp + off) = o;
                }
            }
    } else if (region == 0) {
        // q softmax: warp's 64-col span == one head; quad reduce
        #pragma unroll
        for (int mt = 0; mt < 2; mt++)
            #pragma unroll
            for (int rh = 0; rh < 2; rh++) {
                int m = m0 + mBase + mt*16 + g + rh*8;
                float v0[8], v1[8];
                float mx = -1e30f;
                #pragma unroll
                for (int nt = 0; nt < 8; nt++) {
                    v0[nt] = acc[mt][nt][2*rh]   + blo[nt];
                    v1[nt] = acc[mt][nt][2*rh+1] + bhi[nt];
                    mx = fmaxf(mx, fmaxf(v0[nt], v1[nt]));
                }
                mx = fmaxf(mx, __shfl_xor_sync(0xffffffffu, mx, 1));
                mx = fmaxf(mx, __shfl_xor_sync(0xffffffffu, mx, 2));
                float s = 0.f;
                #pragma unroll
                for (int nt = 0; nt < 8; nt++) {
                    v0[nt] = __expf(v0[nt] - mx); v1[nt] = __expf(v1[nt] - mx);
                    s += v0[nt] + v1[nt];
                }
                s += __shfl_xor_sync(0xffffffffu, s, 1);
                s += __shfl_xor_sync(0xffffffffu, s, 2);
                float inv = 1.f / s;
                #pragma unroll
                for (int nt = 0; nt < 8; nt++)
                    *(__half2*)(g_qs + (size_t)m*Dd + cbase + nt*8) =
                        __floats2half2_rn(v0[nt]*inv, v1[nt]*inv);
            }
    } else if (region == 1) {
        float cs0[8] = {}, cs1[8] = {};
        #pragma unroll
        for (int mt = 0; mt < 2; mt++)
            #pragma unroll
            for (int rh = 0; rh < 2; rh++) {
                int m = m0 + mBase + mt*16 + g + rh*8;
                float madd = (1.f - mask[m]) * (-1e6f);
                #pragma unroll
                for (int nt = 0; nt < 8; nt++) {
                    float e0 = __expf(acc[mt][nt][2*rh]   + blo[nt] + madd);
                    float e1 = __expf(acc[mt][nt][2*rh+1] + bhi[nt] + madd);
                    __half2 h2 = __floats2half2_rn(e0, e1);
                    *(__half2*)(g_ek + (size_t)m*Dd + cbase + nt*8) = h2;
                    float2 hf = __half22float2(h2);
                    cs0[nt] += hf.x; cs1[nt] += hf.y;
                }
            }
        #pragma unroll
        for (int o = 4; o <= 16; o <<= 1)
            #pragma unroll
            for (int nt = 0; nt < 8; nt++) {
                cs0[nt] += __shfl_xor_sync(0xffffffffu, cs0[nt], o);
                cs1[nt] += __shfl_xor_sync(0xffffffffu, cs1[nt], o);
            }
        if (lane < 4) {
            int batch = m0 >> 13;
            #pragma unroll
            for (int nt = 0; nt < 8; nt++) {
                atomicAdd(&g_ksum[batch*Dd + cbase + nt*8],     cs0[nt]);
                atomicAdd(&g_ksum[batch*Dd + cbase + nt*8 + 1], cs1[nt]);
            }
        }
    } else {
        #pragma unroll
        for (int mt = 0; mt < 2; mt++)
            #pragma unroll
            for (int rh = 0; rh < 2; rh++) {
                int m = m0 + mBase + mt*16 + g + rh*8;
                float mv = mask[m];
                #pragma unroll
                for (int nt = 0; nt < 8; nt++)
                    *(__half2*)(g_vv + (size_t)m*Dd + cbase + nt*8) =
                        __floats2half2_rn((acc[mt][nt][2*rh]   + blo[nt])*mv,
                                          (acc[mt][nt][2*rh+1] + bhi[nt])*mv);
            }
    }
}

// ---------------- KV state (tf32 tensor, fp16 inputs) ----------------
__global__ __launch_bounds__(128) void kv_k() {
    __shared__ float Es[64][72];
    __shared__ float Vs[64][72];
    int bh = blockIdx.x; int b = bh >> 3; int h = bh & 7;
    int t0 = b*Tt + blockIdx.y * 512;
    int tid = threadIdx.x;
    int lane = tid & 31, w = tid >> 5;
    int g = lane >> 2, cq = lane & 3;
    int mBase = w * 16;

    float acc[8][4];
    #pragma unroll
    for (int i = 0; i < 8; i++)
        #pragma unroll
        for (int r = 0; r < 4; r++) acc[i][r] = 0.f;

    for (int tile = 0; tile < 8; tile++) {
        #pragma unroll
        for (int i = 0; i < 8; i++) {
            int s = tid + i*128;
            int r = s >> 4, c4 = s & 15;
            size_t base = (size_t)(t0 + tile*64 + r)*Dd + h*DH + c4*4;
            const __half2* pe = (const __half2*)(g_ek + base);
            const __half2* pv = (const __half2*)(g_vv + base);
            float2 e0 = __half22float2(pe[0]), e1 = __half22float2(pe[1]);
            float2 v0 = __half22float2(pv[0]), v1 = __half22float2(pv[1]);
            *(float4*)&Es[r][c4*4] = make_float4(e0.x, e0.y, e1.x, e1.y);
            *(float4*)&Vs[r][c4*4] = make_float4(v0.x, v0.y, v1.x, v1.y);
        }
        __syncthreads();
        #pragma unroll
        for (int k8 = 0; k8 < 8; k8++) {
            int kk = k8*8;
            uint32_t a[4], bfr[8][2];
            a[0] = __float_as_uint(Es[kk+cq][mBase+g]);
            a[1] = __float_as_uint(Es[kk+cq][mBase+g+8]);
            a[2] = __float_as_uint(Es[kk+cq+4][mBase+g]);
            a[3] = __float_as_uint(Es[kk+cq+4][mBase+g+8]);
            #pragma unroll
            for (int nt = 0; nt < 8; nt++) {
                bfr[nt][0] = __float_as_uint(Vs[kk+cq][nt*8+g]);
                bfr[nt][1] = __float_as_uint(Vs[kk+cq+4][nt*8+g]);
            }
            #pragma unroll
            for (int nt = 0; nt < 8; nt++)
                mma_tf32(acc[nt], a, bfr[nt]);
        }
        __syncthreads();
    }
    float* A = g_attn + (size_t)bh*DH*DH;
    #pragma unroll
    for (int nt = 0; nt < 8; nt++) {
        int n = nt*8 + cq*2;
        atomicAdd(&A[(mBase+g)*DH + n],     acc[nt][0]);
        atomicAdd(&A[(mBase+g)*DH + n+1],   acc[nt][1]);
        atomicAdd(&A[(mBase+g+8)*DH + n],   acc[nt][2]);
        atomicAdd(&A[(mBase+g+8)*DH + n+1], acc[nt][3]);
    }
}

// ---------------- y = q_h @ (attn_h / ksum) (tf32 tensor, fp16 in/out) --------
__global__ __launch_bounds__(128) void y_k() {
    __shared__ float Qs[64][68];
    __shared__ float Ahs[64][72];
    int bh = blockIdx.x; int b = bh >> 3; int h = bh & 7;
    int t0 = b*Tt + blockIdx.y * 64;
    int tid = threadIdx.x;
    int lane = tid & 31, w = tid >> 5;
    int g = lane >> 2, cq = lane & 3;
    int mBase = w * 16;

    {
        const float* A  = g_attn + (size_t)bh*DH*DH;
        const float* ks = g_ksum + b*Dd + h*DH;
        #pragma unroll
        for (int i = 0; i < 8; i++) {
            int s = tid + i*128;
            int r = s >> 4, c4 = s & 15;
            float rk = 1.f / ks[r];
            float4 a = *(const float4*)(A + r*DH + c4*4);
            a.x *= rk; a.y *= rk; a.z *= rk; a.w *= rk;
            *(float4*)&Ahs[r][c4*4] = a;
            const __half2* pq = (const __half2*)(g_qs + (size_t)(t0 + r)*Dd + h*DH + c4*4);
            float2 q0 = __half22float2(pq[0]), q1 = __half22float2(pq[1]);
            *(float4*)&Qs[r][c4*4] = make_float4(q0.x, q0.y, q1.x, q1.y);
        }
    }
    __syncthreads();

    float acc[8][4];
    #pragma unroll
    for (int i = 0; i < 8; i++)
        #pragma unroll
        for (int r = 0; r < 4; r++) acc[i][r] = 0.f;

    #pragma unroll
    for (int k8 = 0; k8 < 8; k8++) {
        int kk = k8*8;
        uint32_t a[4], bfr[8][2];
        a[0] = __float_as_uint(Qs[mBase+g][kk+cq]);
        a[1] = __float_as_uint(Qs[mBase+g+8][kk+cq]);
        a[2] = __float_as_uint(Qs[mBase+g][kk+cq+4]);
        a[3] = __float_as_uint(Qs[mBase+g+8][kk+cq+4]);
        #pragma unroll
        for (int nt = 0; nt < 8; nt++) {
            bfr[nt][0] = __float_as_uint(Ahs[kk+cq][nt*8+g]);
            bfr[nt][1] = __float_as_uint(Ahs[kk+cq+4][nt*8+g]);
        }
        #pragma unroll
        for (int nt = 0; nt < 8; nt++)
            mma_tf32(acc[nt], a, bfr[nt]);
    }

    #pragma unroll
    for (int nt = 0; nt < 8; nt++) {
        int n = h*DH + nt*8 + cq*2;
        size_t r0 = (size_t)(t0 + mBase + g)*Dd + n;
        size_t r1 = (size_t)(t0 + mBase + g + 8)*Dd + n;
        *(__half2*)(g_y + r0) = __floats2half2_rn(acc[nt][0], acc[nt][1]);
        *(__half2*)(g_y + r1) = __floats2half2_rn(acc[nt][2], acc[nt][3]);
    }
}

// ---------------- stylize + silu -> g_hs (fp16 in/out) ----------------
__global__ void style_k(const float* __restrict__ g2, const float* __restrict__ b2) {
    int tok = blockIdx.x, tid = threadIdx.x;
    int b = tok >> 13;
    const __half2* py = (const __half2*)(g_y + (size_t)tok*Dd);
    float2 y01 = __half22float2(py[tid*2]);
    float2 y23 = __half22float2(py[tid*2+1]);
    float s = y01.x + y01.y + y23.x + y23.y;
    __shared__ float r1[4], r2[4];
    for (int o = 16; o; o >>= 1) s += __shfl_xor_sync(0xffffffffu, s, o);
    if ((tid & 31) == 0) r1[tid >> 5] = s;
    __syncthreads();
    float mu = (r1[0] + r1[1] + r1[2] + r1[3]) * (1.f / Dd);
    float a = y01.x - mu, bb_ = y01.y - mu, c = y23.x - mu, d = y23.y - mu;
    float ss = a*a + bb_*bb_ + c*c + d*d;
    for (int o = 16; o; o >>= 1) ss += __shfl_xor_sync(0xffffffffu, ss, o);
    if ((tid & 31) == 0) r2[tid >> 5] = ss;
    __syncthreads();
    float var = (r2[0] + r2[1] + r2[2] + r2[3]) * (1.f / Dd);
    float rs = rsqrtf(var + 1e-5f);
    float4 gg = ((const float4*)g2)[tid], bt = ((const float4*)b2)[tid];
    float4 sc = ((const float4*)(g_emb + b*2*Dd))[tid];
    float4 sh = ((const float4*)(g_emb + b*2*Dd + Dd))[tid];
    float h0 = (a  *rs*gg.x + bt.x)*(1.f + sc.x) + sh.x;
    float h1 = (bb_*rs*gg.y + bt.y)*(1.f + sc.y) + sh.y;
    float h2 = (c  *rs*gg.z + bt.z)*(1.f + sc.z) + sh.z;
    float h3 = (d  *rs*gg.w + bt.w)*(1.f + sc.w) + sh.w;
    h0 = h0 / (1.f + __expf(-h0));
    h1 = h1 / (1.f + __expf(-h1));
    h2 = h2 / (1.f + __expf(-h2));
    h3 = h3 / (1.f + __expf(-h3));
    __half2* ph = (__half2*)(g_hs + (size_t)tok*Dd);
    ph[tid*2]   = __halves2half2(__float2half_rn(h0), __float2half_rn(h1));
    ph[tid*2+1] = __halves2half2(__float2half_rn(h2), __float2half_rn(h3));
}

// ---------------- launch ----------------
extern "C" void kernel_launch(void* const* d_in, const int* in_sizes, int n_in,
                              void* d_out, int out_size) {
    const float* x     = (const float*)d_in[0];
    const float* emb   = (const float*)d_in[1];
    const float* mask  = (const float*)d_in[2];
    const float* gamma = (const float*)d_in[3];
    const float* beta  = (const float*)d_in[4];
    const float* Wq    = (const float*)d_in[5];
    const float* bq    = (const float*)d_in[6];
    const float* Wk    = (const float*)d_in[7];
    const float* bk    = (const float*)d_in[8];
    const float* Wv    = (const float*)d_in[9];
    const float* bv    = (const float*)d_in[10];
    const float* embW  = (const float*)d_in[11];
    const float* embB  = (const float*)d_in[12];
    const float* g2    = (const float*)d_in[13];
    const float* b2    = (const float*)d_in[14];
    const float* outW  = (const float*)d_in[15];
    const float* outB  = (const float*)d_in[16];
    float* out = (float*)d_out;

    static int inited = 0;
    static cudaStream_t s2;
    static cudaEvent_t ev0, ev1;
    if (!inited) {
        cudaFuncSetAttribute(gemm_k, cudaFuncAttributeMaxDynamicSharedMemorySize, SMEM_BYTES);
        cudaStreamCreateWithFlags(&s2, cudaStreamNonBlocking);
        cudaEventCreateWithFlags(&ev0, cudaEventDisableTiming);
        cudaEventCreateWithFlags(&ev1, cudaEventDisableTiming);
        inited = 1;
    }

    // fork: {wconv, emb} on s2 || {ln} on main; join before QKV GEMM
    zero_k <<<512, 256>>>(embB);
    cudaEventRecord(ev0, 0);
    cudaStreamWaitEvent(s2, ev0, 0);
    wconv_k<<<dim3(16, 16, 4), dim3(32, 8), 0, s2>>>(Wq, Wk, Wv, outW);
    emb_k  <<<dim3(Bb, 8, 8), 256, 0, s2>>>(emb, embW);
    cudaEventRecord(ev1, s2);
    ln_k   <<<NTOK, 128>>>(x, gamma, beta);
    cudaStreamWaitEvent(0, ev1, 0);

    gemm_k <<<dim3(12, NTOK/128), 256, SMEM_BYTES>>>(0, bq, bk, bv, mask, nullptr, nullptr);
    kv_k   <<<dim3(Bb*Hh, 16), 128>>>();
    y_k    <<<dim3(Bb*Hh, Tt/64), 128>>>();
    style_k<<<NTOK, 128>>>(g2, b2);
    gemm_k <<<dim3(4, NTOK/128), 256, SMEM_BYTES>>>(1, outB, nullptr, nullptr, nullptr, x, out);
}